// round 9
// baseline (speedup 1.0000x reference)
#include <cuda_runtime.h>
#include <cuda_bf16.h>
#include <math.h>
#include <stdint.h>

#define NN 20000
#define EE 320000
#define HH 128
#define NTILES_N ((NN + 63) / 64)   /* 313 */
#define ETILE 64
#define NTILES_E (EE / ETILE)       /* 5000 */

extern __shared__ char smraw[];

/* ---------------- scratch (static device globals; no allocations) -------- */
__device__ float g_g1[NN * HH];   /* h[dst]-part of layer1 (+eb1)  */
__device__ float g_g2[NN * HH];   /* h[src]-part of layer1         */
__device__ float g_mi[NN * HH];   /* segment sum of mij*eij        */
__device__ float g_tmp[NN * HH];  /* node MLP hidden               */
__device__ float g_dx[NN * 3];    /* segment sum of rel_x*xg       */

/* ---------------- small helpers ------------------------------------------ */
__device__ __forceinline__ void red4(float* p, float a, float b, float c, float d) {
    asm volatile("red.global.add.v4.f32 [%0], {%1,%2,%3,%4};"
                 :: "l"(p), "f"(a), "f"(b), "f"(c), "f"(d) : "memory");
}
__device__ __forceinline__ uint32_t smem_u32(const void* p) {
    uint32_t a;
    asm("{ .reg .u64 t; cvta.to.shared.u64 t, %1; cvt.u32.u64 %0, t; }"
        : "=r"(a) : "l"(p));
    return a;
}
/* pack (low half = a, high half = b) */
#define PACKBF2(res, a, b) \
    asm("cvt.rn.satfinite.bf16x2.f32 %0, %1, %2;" : "=r"(res) : "f"(b), "f"(a))
__device__ __forceinline__ void split2(float a0, float a1, uint32_t& hw, uint32_t& lw) {
    PACKBF2(hw, a0, a1);
    float h0 = __uint_as_float(hw << 16);
    float h1 = __uint_as_float(hw & 0xffff0000u);
    PACKBF2(lw, a0 - h0, a1 - h1);
}

/* ---------------- mma / ldmatrix ----------------------------------------- */
#define LDSM4(r, a) \
    asm volatile("ldmatrix.sync.aligned.m8n8.x4.shared.b16 {%0,%1,%2,%3},[%4];" \
        : "=r"((r)[0]), "=r"((r)[1]), "=r"((r)[2]), "=r"((r)[3]) : "r"(a))
#define MMA_B16(d, a, b0, b1) \
    asm volatile("mma.sync.aligned.m16n8k16.row.col.f32.bf16.bf16.f32 " \
        "{%0,%1,%2,%3},{%4,%5,%6,%7},{%8,%9},{%0,%1,%2,%3};" \
        : "+f"((d)[0]), "+f"((d)[1]), "+f"((d)[2]), "+f"((d)[3]) \
        : "r"((a)[0]), "r"((a)[1]), "r"((a)[2]), "r"((a)[3]), "r"(b0), "r"(b1))

/* XOR-swizzled bf16 tile: row r, 16B chunk c -> phys chunk (c&~7)|((c&7)^(r&7)) */
__device__ __forceinline__ uint32_t pch(int c, int r) {
    return (uint32_t)((c & ~7) | ((c & 7) ^ (r & 7)));
}

/* warp GEMM: D[16 rows x (16*NJP) cols] += A[16xK] * B[K x 16*NJP]^T */
template<int KSTEPS, bool X3, int CA, int CB, int NJP>
__device__ __forceinline__ void mma_gemm(const char* aH, const char* aL,
                                         const char* bH, const char* bL,
                                         float acc[][4], int wm, int wn, int lane) {
    int ar7 = lane & 7;
    int arow = 16 * wm + ((lane >> 3) & 1) * 8 + ar7;
    int acoff = lane >> 4;
    int brow_l = ((lane >> 4) & 1) * 8 + ar7;
    int bcoff = (lane >> 3) & 1;
    uint32_t aHb = smem_u32(aH) + (uint32_t)(arow * CA);
    uint32_t aLb = X3 ? (smem_u32(aL) + (uint32_t)(arow * CA)) : 0u;
    uint32_t bHb = smem_u32(bH);
    uint32_t bLb = X3 ? smem_u32(bL) : 0u;
#pragma unroll
    for (int ks = 0; ks < KSTEPS; ks++) {
        uint32_t aoff = pch(2 * ks + acoff, ar7) * 16;
        uint32_t ah[4], al[4];
        LDSM4(ah, aHb + aoff);
        if (X3) LDSM4(al, aLb + aoff);
        uint32_t boff = pch(2 * ks + bcoff, ar7) * 16;
#pragma unroll
        for (int jp = 0; jp < NJP; jp++) {
            uint32_t brb = (uint32_t)((wn * (16 * NJP) + jp * 16 + brow_l) * CB) + boff;
            uint32_t bh[4];
            LDSM4(bh, bHb + brb);
            MMA_B16(acc[2 * jp],     ah, bh[0], bh[1]);
            MMA_B16(acc[2 * jp + 1], ah, bh[2], bh[3]);
            if (X3) {
                uint32_t bl[4];
                LDSM4(bl, bLb + brb);
                MMA_B16(acc[2 * jp],     al, bh[0], bh[1]);
                MMA_B16(acc[2 * jp + 1], al, bh[2], bh[3]);
                MMA_B16(acc[2 * jp],     ah, bl[0], bl[1]);
                MMA_B16(acc[2 * jp + 1], ah, bl[2], bl[3]);
            }
        }
    }
}

/* stage D fragments -> fp32 smem [64][128], 16B-chunk swizzled (512B rows) */
template<int NJP>
__device__ __forceinline__ void stage_D(char* DS, const float acc[][4],
                                        int wm, int wn, int lane) {
    int r0 = 16 * wm + (lane >> 2);
    int r1 = r0 + 8;
    int cbase = wn * (16 * NJP) + 2 * (lane & 3);
#pragma unroll
    for (int j = 0; j < 2 * NJP; j++) {
        int cc = cbase + 8 * j;
        int ch = cc >> 2, inoff = (cc & 3) * 4;
        *(float2*)(DS + r0 * 512 + pch(ch, r0) * 16 + inoff) =
            make_float2(acc[j][0], acc[j][1]);
        *(float2*)(DS + r1 * 512 + pch(ch, r1) * 16 + inoff) =
            make_float2(acc[j][2], acc[j][3]);
    }
}

/* ================= kernel A: per-node precompute (MMA) + zero scratch ==== */
/* smem: W1H 0(32K) W1L 32K W2H 64K W2L 96K AH 128K(16K) AL 144K DS 160K(32K)
 *       EB1 192K(512)  total 197120 */
#define NP_W1H 0
#define NP_W1L 32768
#define NP_W2H 65536
#define NP_W2L 98304
#define NP_AH  131072
#define NP_AL  147456
#define NP_DS  163840
#define NP_EB1 196608
#define NP_TOTAL 197120

__global__ void __launch_bounds__(512, 1)
k_node_pre(const float* __restrict__ h, const float* __restrict__ ew1,
           const float* __restrict__ eb1) {
    char* sm = smraw;
    int tid = threadIdx.x, lane = tid & 31, wid = tid >> 5;
    int wm = wid >> 2, wn = wid & 3;
    int n0 = blockIdx.x * 64;

    /* zero mi / dx for this node tile */
    for (int i = tid; i < 64 * 128; i += 512) {
        int n = n0 + (i >> 7);
        if (n < NN) g_mi[n * 128 + (i & 127)] = 0.f;
    }
    if (tid < 192) {
        int n = n0 + tid / 3;
        if (n < NN) g_dx[n * 3 + tid % 3] = 0.f;
    }
    /* weights: W1[n][k]=ew1[(48+k)*128+n], W2[n][k]=ew1[(176+k)*128+n] */
    for (int i = tid; i < 128 * 64; i += 512) {
        int n = i >> 6, kp = i & 63, k = 2 * kp;
        uint32_t off = (uint32_t)(n * 256) + pch(k >> 3, n) * 16 + (k & 7) * 2;
        uint32_t hw, lw;
        split2(ew1[(48 + k) * 128 + n], ew1[(49 + k) * 128 + n], hw, lw);
        *(uint32_t*)(sm + NP_W1H + off) = hw;
        *(uint32_t*)(sm + NP_W1L + off) = lw;
        split2(ew1[(176 + k) * 128 + n], ew1[(177 + k) * 128 + n], hw, lw);
        *(uint32_t*)(sm + NP_W2H + off) = hw;
        *(uint32_t*)(sm + NP_W2L + off) = lw;
    }
    /* A: h tile [64][128] */
    for (int i = tid; i < 64 * 64; i += 512) {
        int r = i >> 6, kp = i & 63, k = 2 * kp, n = n0 + r;
        float2 v = (n < NN) ? *(const float2*)&h[n * 128 + k] : make_float2(0.f, 0.f);
        uint32_t hw, lw; split2(v.x, v.y, hw, lw);
        uint32_t off = (uint32_t)(r * 256) + pch(k >> 3, r) * 16 + (k & 7) * 2;
        *(uint32_t*)(sm + NP_AH + off) = hw;
        *(uint32_t*)(sm + NP_AL + off) = lw;
    }
    if (tid < 128) ((float*)(sm + NP_EB1))[tid] = eb1[tid];
    __syncthreads();

    float acc[4][4];
#pragma unroll
    for (int j = 0; j < 4; j++)
#pragma unroll
        for (int q = 0; q < 4; q++) acc[j][q] = 0.f;
    mma_gemm<8, true, 256, 256, 2>(sm + NP_AH, sm + NP_AL,
                                   sm + NP_W1H, sm + NP_W1L, acc, wm, wn, lane);
    stage_D<2>(sm + NP_DS, acc, wm, wn, lane);
    __syncthreads();
    for (int i = tid; i < 64 * 32; i += 512) {
        int r = i >> 5, ch = i & 31, n = n0 + r;
        if (n < NN) {
            float4 dv = *(const float4*)(sm + NP_DS + r * 512 + pch(ch, r) * 16);
            float4 bb = *(const float4*)(sm + NP_EB1 + ch * 16);
            *(float4*)&g_g1[(size_t)n * 128 + ch * 4] =
                make_float4(dv.x + bb.x, dv.y + bb.y, dv.z + bb.z, dv.w + bb.w);
        }
    }
    __syncthreads();
#pragma unroll
    for (int j = 0; j < 4; j++)
#pragma unroll
        for (int q = 0; q < 4; q++) acc[j][q] = 0.f;
    mma_gemm<8, true, 256, 256, 2>(sm + NP_AH, sm + NP_AL,
                                   sm + NP_W2H, sm + NP_W2L, acc, wm, wn, lane);
    stage_D<2>(sm + NP_DS, acc, wm, wn, lane);
    __syncthreads();
    for (int i = tid; i < 64 * 32; i += 512) {
        int r = i >> 5, ch = i & 31, n = n0 + r;
        if (n < NN)
            *(float4*)&g_g2[(size_t)n * 128 + ch * 4] =
                *(const float4*)(sm + NP_DS + r * 512 + pch(ch, r) * 16);
    }
}

/* ================= kernel B: mma.sync bf16 edge pipeline (unchanged) ===== */
#define SB_DST   0
#define SB_SRC   256
#define SB_RELX  512
#define SB_XL2   1280
#define SB_EB2   1536
#define SB_XB1   2048
#define SB_INFW  2560
#define SB_XW2   3072
#define SB_FEATH 4096
#define SB_FEATL 12288
#define SB_BUFM  4096
#define SB_TH    20480
#define SB_TL    36864
#define SB_DS    53248
#define SB_W1H   86016
#define SB_W1L   102400
#define SB_W2H   118784
#define SB_W2L   151552
#define SB_W3H   184320
#define SB_TOTAL 217088

__global__ void __launch_bounds__(256, 1)
k_edge(const float* __restrict__ x, const float* __restrict__ eattr,
       const float* __restrict__ ew1, const float* __restrict__ ew2,
       const float* __restrict__ eb2, const float* __restrict__ infw,
       const float* __restrict__ infb, const float* __restrict__ xw1,
       const float* __restrict__ xb1, const float* __restrict__ xw2,
       const float* __restrict__ xb2, const int* __restrict__ eidx) {
    char* sm = smraw;
    int* dsts = (int*)(sm + SB_DST);
    int* srcs = (int*)(sm + SB_SRC);
    float* relxs = (float*)(sm + SB_RELX);
    float* xl2s  = (float*)(sm + SB_XL2);
    float* eb2s  = (float*)(sm + SB_EB2);
    float* xb1s  = (float*)(sm + SB_XB1);
    float* infws = (float*)(sm + SB_INFW);
    float* xw2s  = (float*)(sm + SB_XW2);

    int tid = threadIdx.x;
    int lane = tid & 31;
    int wid = tid >> 5;
    int wm = wid >> 1, wn = wid & 1;
    int rg = wid, cg = lane;

    for (int i = tid; i < 128 * 64; i += 256) {
        int n = i >> 6, k = i & 63;
        float v = (k < 48) ? ew1[k * 128 + n] : 0.f;
        __nv_bfloat16 hb = __float2bfloat16(v);
        uint32_t off = (uint32_t)(n * 128) + pch(k >> 3, n) * 16 + (k & 7) * 2;
        *(__nv_bfloat16*)(sm + SB_W1H + off) = hb;
        *(__nv_bfloat16*)(sm + SB_W1L + off) =
            __float2bfloat16(v - __bfloat162float(hb));
    }
    for (int i = tid; i < 128 * 128; i += 256) {
        int n = i >> 7, k = i & 127;
        uint32_t off = (uint32_t)(n * 256) + pch(k >> 3, n) * 16 + (k & 7) * 2;
        float v = ew2[k * 128 + n];
        __nv_bfloat16 hb = __float2bfloat16(v);
        *(__nv_bfloat16*)(sm + SB_W2H + off) = hb;
        *(__nv_bfloat16*)(sm + SB_W2L + off) =
            __float2bfloat16(v - __bfloat162float(hb));
        *(__nv_bfloat16*)(sm + SB_W3H + off) = __float2bfloat16(xw1[k * 128 + n]);
    }
    if (tid < 128) {
        eb2s[tid] = eb2[tid]; xb1s[tid] = xb1[tid];
        infws[tid] = infw[tid]; xw2s[tid] = xw2[tid];
    }
    __syncthreads();

    float eb2r[4], infwr[4], xb1r[4], xw2r[4];
#pragma unroll
    for (int j = 0; j < 4; j++) {
        eb2r[j] = eb2s[cg * 4 + j]; infwr[j] = infws[cg * 4 + j];
        xb1r[j] = xb1s[cg * 4 + j]; xw2r[j] = xw2s[cg * 4 + j];
    }
    const float infbv = infb[0];
    const float xb2v  = xb2[0];
    const float step  = 100.0f / 19.0f;
    const float coeff = -0.5f / (step * step);

    for (int tile = blockIdx.x; tile < NTILES_E; tile += gridDim.x) {
        __syncthreads();
        int e0 = tile * ETILE;

        if (tid < 64) {
            int e = e0 + tid;
            int d = eidx[e], s = eidx[EE + e];
            dsts[tid] = d; srcs[tid] = s;
            float rx = x[d * 3 + 0] - x[s * 3 + 0];
            float ry = x[d * 3 + 1] - x[s * 3 + 1];
            float rz = x[d * 3 + 2] - x[s * 3 + 2];
            relxs[tid * 3 + 0] = rx; relxs[tid * 3 + 1] = ry; relxs[tid * 3 + 2] = rz;
            xl2s[tid] = sqrtf(rx * rx + ry * ry + rz * rz);
        }
        for (int i = tid; i < 64 * 14; i += 256) {
            int e = i / 14, w = i - 14 * e;
            float2 t = *(const float2*)&eattr[(size_t)(e0 + e) * 28 + 2 * w];
            uint32_t hw, lw; split2(t.x, t.y, hw, lw);
            uint32_t off = (uint32_t)(e * 128) + pch(w >> 2, e) * 16 + (w & 3) * 4;
            *(uint32_t*)(sm + SB_FEATH + off) = hw;
            *(uint32_t*)(sm + SB_FEATL + off) = lw;
        }
        __syncthreads();

        for (int i = tid; i < 64 * 10; i += 256) {
            int e = i / 10, w = 14 + (i - 10 * e);
            int k0 = 2 * w - 28;
            float l2v = xl2s[e];
            float d0 = l2v - (float)k0 * step, d1 = l2v - (float)(k0 + 1) * step;
            uint32_t hw, lw;
            split2(expf(coeff * d0 * d0), expf(coeff * d1 * d1), hw, lw);
            uint32_t off = (uint32_t)(e * 128) + pch(w >> 2, e) * 16 + (w & 3) * 4;
            *(uint32_t*)(sm + SB_FEATH + off) = hw;
            *(uint32_t*)(sm + SB_FEATL + off) = lw;
        }
        int dr[8], sr[8];
#pragma unroll
        for (int i = 0; i < 8; i++) { dr[i] = dsts[rg * 8 + i]; sr[i] = srcs[rg * 8 + i]; }
        __syncthreads();

        float acc[8][4];
#pragma unroll
        for (int j = 0; j < 8; j++)
#pragma unroll
            for (int q = 0; q < 4; q++) acc[j][q] = 0.f;
        mma_gemm<3, true, 128, 128, 4>(sm + SB_FEATH, sm + SB_FEATL,
                                       sm + SB_W1H, sm + SB_W1L, acc, wm, wn, lane);
        stage_D<4>(sm + SB_DS, acc, wm, wn, lane);
        __syncthreads();

#pragma unroll
        for (int i = 0; i < 8; i++) {
            int e = rg * 8 + i;
            float4 dv = *(const float4*)(sm + SB_DS + e * 512 + pch(cg, e) * 16);
            float4 a = *(const float4*)&g_g1[(size_t)dr[i] * 128 + cg * 4];
            float4 b = *(const float4*)&g_g2[(size_t)sr[i] * 128 + cg * 4];
            float v0 = fmaxf(dv.x + a.x + b.x, 0.f);
            float v1 = fmaxf(dv.y + a.y + b.y, 0.f);
            float v2 = fmaxf(dv.z + a.z + b.z, 0.f);
            float v3 = fmaxf(dv.w + a.w + b.w, 0.f);
            uint32_t h0, l0, h1, l1;
            split2(v0, v1, h0, l0); split2(v2, v3, h1, l1);
            uint32_t off = (uint32_t)(e * 256) + pch(cg >> 1, e) * 16 + (cg & 1) * 8;
            *(uint2*)(sm + SB_TH + off) = make_uint2(h0, h1);
            *(uint2*)(sm + SB_TL + off) = make_uint2(l0, l1);
        }
        __syncthreads();

#pragma unroll
        for (int j = 0; j < 8; j++)
#pragma unroll
            for (int q = 0; q < 4; q++) acc[j][q] = 0.f;
        mma_gemm<8, true, 256, 256, 4>(sm + SB_TH, sm + SB_TL,
                                       sm + SB_W2H, sm + SB_W2L, acc, wm, wn, lane);
        stage_D<4>(sm + SB_DS, acc, wm, wn, lane);
        __syncthreads();

        float pd[8];
        float mv[8][4];
#pragma unroll
        for (int i = 0; i < 8; i++) {
            int e = rg * 8 + i;
            float4 dv = *(const float4*)(sm + SB_DS + e * 512 + pch(cg, e) * 16);
            float m0 = fmaxf(dv.x + eb2r[0], 0.f);
            float m1 = fmaxf(dv.y + eb2r[1], 0.f);
            float m2 = fmaxf(dv.z + eb2r[2], 0.f);
            float m3 = fmaxf(dv.w + eb2r[3], 0.f);
            mv[i][0] = m0; mv[i][1] = m1; mv[i][2] = m2; mv[i][3] = m3;
            pd[i] = m0 * infwr[0] + m1 * infwr[1] + m2 * infwr[2] + m3 * infwr[3];
            uint32_t w0, w1;
            PACKBF2(w0, m0, m1); PACKBF2(w1, m2, m3);
            uint32_t off = (uint32_t)(e * 256) + pch(cg >> 1, e) * 16 + (cg & 1) * 8;
            *(uint2*)(sm + SB_BUFM + off) = make_uint2(w0, w1);
        }
#pragma unroll
        for (int o = 16; o > 0; o >>= 1)
#pragma unroll
            for (int i = 0; i < 8; i++)
                pd[i] += __shfl_xor_sync(0xffffffffu, pd[i], o);
#pragma unroll
        for (int i = 0; i < 8; i++) {
            float eij = 1.f / (1.f + expf(-(pd[i] + infbv)));
            red4(&g_mi[(size_t)dr[i] * 128 + cg * 4],
                 mv[i][0] * eij, mv[i][1] * eij, mv[i][2] * eij, mv[i][3] * eij);
        }
        __syncthreads();

#pragma unroll
        for (int j = 0; j < 8; j++)
#pragma unroll
            for (int q = 0; q < 4; q++) acc[j][q] = 0.f;
        mma_gemm<8, false, 256, 256, 4>(sm + SB_BUFM, 0,
                                        sm + SB_W3H, 0, acc, wm, wn, lane);
        stage_D<4>(sm + SB_DS, acc, wm, wn, lane);
        __syncthreads();

        float q[8];
#pragma unroll
        for (int i = 0; i < 8; i++) {
            int e = rg * 8 + i;
            float4 dv = *(const float4*)(sm + SB_DS + e * 512 + pch(cg, e) * 16);
            q[i] = fmaxf(dv.x + xb1r[0], 0.f) * xw2r[0]
                 + fmaxf(dv.y + xb1r[1], 0.f) * xw2r[1]
                 + fmaxf(dv.z + xb1r[2], 0.f) * xw2r[2]
                 + fmaxf(dv.w + xb1r[3], 0.f) * xw2r[3];
        }
#pragma unroll
        for (int o = 16; o > 0; o >>= 1)
#pragma unroll
            for (int i = 0; i < 8; i++)
                q[i] += __shfl_xor_sync(0xffffffffu, q[i], o);
        if (cg < 3) {
#pragma unroll
            for (int i = 0; i < 8; i++) {
                float xg = q[i] + xb2v;
                atomicAdd(&g_dx[dr[i] * 3 + cg],
                          relxs[(rg * 8 + i) * 3 + cg] * xg);
            }
        }
    }
}

/* ================= kernel C1: hidden = relu([mi,h]@nw1+nb1) (MMA) ======== */
/* smem: WH 0(64K) WL 64K AH 128K(32K) AL 160K DS 192K(32K) B 224K(512)
 * total 229888 */
#define N1_WH 0
#define N1_WL 65536
#define N1_AH 131072
#define N1_AL 163840
#define N1_DS 196608
#define N1_B  229376
#define N1_TOTAL 229888

__global__ void __launch_bounds__(512, 1)
k_node1(const float* __restrict__ h, const float* __restrict__ nw1,
        const float* __restrict__ nb1) {
    char* sm = smraw;
    int tid = threadIdx.x, lane = tid & 31, wid = tid >> 5;
    int wm = wid >> 2, wn = wid & 3;
    int n0 = blockIdx.x * 64;

    /* W[n][k] = nw1[k*128+n], K=256 */
    for (int i = tid; i < 128 * 128; i += 512) {
        int n = i >> 7, kp = i & 127, k = 2 * kp;
        uint32_t off = (uint32_t)(n * 512) + pch(k >> 3, n) * 16 + (k & 7) * 2;
        uint32_t hw, lw;
        split2(nw1[k * 128 + n], nw1[(k + 1) * 128 + n], hw, lw);
        *(uint32_t*)(sm + N1_WH + off) = hw;
        *(uint32_t*)(sm + N1_WL + off) = lw;
    }
    /* A = [mi | h] 64 x 256 */
    for (int i = tid; i < 64 * 128; i += 512) {
        int r = i >> 7, kp = i & 127, k = 2 * kp, n = n0 + r;
        float2 v = make_float2(0.f, 0.f);
        if (n < NN)
            v = (k < 128) ? *(const float2*)&g_mi[(size_t)n * 128 + k]
                          : *(const float2*)&h[(size_t)n * 128 + (k - 128)];
        uint32_t hw, lw; split2(v.x, v.y, hw, lw);
        uint32_t off = (uint32_t)(r * 512) + pch(k >> 3, r) * 16 + (k & 7) * 2;
        *(uint32_t*)(sm + N1_AH + off) = hw;
        *(uint32_t*)(sm + N1_AL + off) = lw;
    }
    if (tid < 128) ((float*)(sm + N1_B))[tid] = nb1[tid];
    __syncthreads();

    float acc[4][4];
#pragma unroll
    for (int j = 0; j < 4; j++)
#pragma unroll
        for (int q = 0; q < 4; q++) acc[j][q] = 0.f;
    mma_gemm<16, true, 512, 512, 2>(sm + N1_AH, sm + N1_AL,
                                    sm + N1_WH, sm + N1_WL, acc, wm, wn, lane);
    stage_D<2>(sm + N1_DS, acc, wm, wn, lane);
    __syncthreads();

    for (int i = tid; i < 64 * 32; i += 512) {
        int r = i >> 5, ch = i & 31, n = n0 + r;
        if (n < NN) {
            float4 dv = *(const float4*)(sm + N1_DS + r * 512 + pch(ch, r) * 16);
            float4 bb = *(const float4*)(sm + N1_B + ch * 16);
            *(float4*)&g_tmp[(size_t)n * 128 + ch * 4] =
                make_float4(fmaxf(dv.x + bb.x, 0.f), fmaxf(dv.y + bb.y, 0.f),
                            fmaxf(dv.z + bb.z, 0.f), fmaxf(dv.w + bb.w, 0.f));
        }
    }
}

/* ================= kernel C2: out = hidden@nw2+nb2 (MMA) ================= */
#define N2_WH 0
#define N2_WL 32768
#define N2_AH 65536
#define N2_AL 81920
#define N2_DS 98304
#define N2_B  131072
#define N2_TOTAL 131584

__global__ void __launch_bounds__(512, 1)
k_node2(const float* __restrict__ nw2, const float* __restrict__ nb2,
        float* __restrict__ out) {
    char* sm = smraw;
    int tid = threadIdx.x, lane = tid & 31, wid = tid >> 5;
    int wm = wid >> 2, wn = wid & 3;
    int n0 = blockIdx.x * 64;

    for (int i = tid; i < 128 * 64; i += 512) {
        int n = i >> 6, kp = i & 63, k = 2 * kp;
        uint32_t off = (uint32_t)(n * 256) + pch(k >> 3, n) * 16 + (k & 7) * 2;
        uint32_t hw, lw;
        split2(nw2[k * 128 + n], nw2[(k + 1) * 128 + n], hw, lw);
        *(uint32_t*)(sm + N2_WH + off) = hw;
        *(uint32_t*)(sm + N2_WL + off) = lw;
    }
    for (int i = tid; i < 64 * 64; i += 512) {
        int r = i >> 6, kp = i & 63, k = 2 * kp, n = n0 + r;
        float2 v = (n < NN) ? *(const float2*)&g_tmp[(size_t)n * 128 + k]
                            : make_float2(0.f, 0.f);
        uint32_t hw, lw; split2(v.x, v.y, hw, lw);
        uint32_t off = (uint32_t)(r * 256) + pch(k >> 3, r) * 16 + (k & 7) * 2;
        *(uint32_t*)(sm + N2_AH + off) = hw;
        *(uint32_t*)(sm + N2_AL + off) = lw;
    }
    if (tid < 128) ((float*)(sm + N2_B))[tid] = nb2[tid];
    __syncthreads();

    float acc[4][4];
#pragma unroll
    for (int j = 0; j < 4; j++)
#pragma unroll
        for (int q = 0; q < 4; q++) acc[j][q] = 0.f;
    mma_gemm<8, true, 256, 256, 2>(sm + N2_AH, sm + N2_AL,
                                   sm + N2_WH, sm + N2_WL, acc, wm, wn, lane);
    stage_D<2>(sm + N2_DS, acc, wm, wn, lane);
    __syncthreads();

    for (int i = tid; i < 64 * 32; i += 512) {
        int r = i >> 5, ch = i & 31, n = n0 + r;
        if (n < NN) {
            float4 dv = *(const float4*)(sm + N2_DS + r * 512 + pch(ch, r) * 16);
            float4 bb = *(const float4*)(sm + N2_B + ch * 16);
            *(float4*)&out[(size_t)n * 128 + ch * 4] =
                make_float4(dv.x + bb.x, dv.y + bb.y, dv.z + bb.z, dv.w + bb.w);
        }
    }
}

/* ================= kernel X: x_out = x + dx/E ============================ */
__global__ void k_xupd(const float* __restrict__ x, float* __restrict__ out) {
    int i = blockIdx.x * blockDim.x + threadIdx.x;
    if (i < NN * 3)
        out[NN * 128 + i] = x[i] + g_dx[i] * (1.0f / (float)EE);
}

/* ========================================================================= */
extern "C" void kernel_launch(void* const* d_in, const int* in_sizes, int n_in,
                              void* d_out, int out_size) {
    const float* h    = (const float*)d_in[0];
    const float* x    = (const float*)d_in[1];
    const float* ea   = (const float*)d_in[2];
    const float* ew1  = (const float*)d_in[3];
    const float* eb1  = (const float*)d_in[4];
    const float* ew2  = (const float*)d_in[5];
    const float* eb2  = (const float*)d_in[6];
    const float* infw = (const float*)d_in[7];
    const float* infb = (const float*)d_in[8];
    const float* nw1  = (const float*)d_in[9];
    const float* nb1  = (const float*)d_in[10];
    const float* nw2  = (const float*)d_in[11];
    const float* nb2  = (const float*)d_in[12];
    const float* xw1  = (const float*)d_in[13];
    const float* xb1  = (const float*)d_in[14];
    const float* xw2  = (const float*)d_in[15];
    const float* xb2  = (const float*)d_in[16];
    const int*   ei   = (const int*)d_in[17];
    float* out = (float*)d_out;

    cudaFuncSetAttribute(k_node_pre, cudaFuncAttributeMaxDynamicSharedMemorySize, NP_TOTAL);
    cudaFuncSetAttribute(k_edge,     cudaFuncAttributeMaxDynamicSharedMemorySize, SB_TOTAL);
    cudaFuncSetAttribute(k_node1,    cudaFuncAttributeMaxDynamicSharedMemorySize, N1_TOTAL);
    cudaFuncSetAttribute(k_node2,    cudaFuncAttributeMaxDynamicSharedMemorySize, N2_TOTAL);

    k_node_pre<<<NTILES_N, 512, NP_TOTAL>>>(h, ew1, eb1);
    k_edge<<<148, 256, SB_TOTAL>>>(x, ea, ew1, ew2, eb2, infw, infb,
                                   xw1, xb1, xw2, xb2, ei);
    k_node1<<<NTILES_N, 512, N1_TOTAL>>>(h, nw1, nb1);
    k_node2<<<NTILES_N, 512, N2_TOTAL>>>(nw2, nb2, out);
    k_xupd<<<(NN * 3 + 255) / 256, 256>>>(x, out);
}

// round 11
// speedup vs baseline: 1.1111x; 1.1111x over previous
#include <cuda_runtime.h>
#include <cuda_bf16.h>
#include <math.h>
#include <stdint.h>

#define NN 20000
#define EE 320000
#define HH 128
#define NTILES_N ((NN + 63) / 64)   /* 313 */
#define ETILE 64
#define NTILES_E (EE / ETILE)       /* 5000 */

extern __shared__ char smraw[];

/* ---------------- scratch (static device globals; no allocations) -------- */
__device__ float g_g1[NN * HH];   /* h[dst]-part of layer1 (+eb1)  */
__device__ float g_g2[NN * HH];   /* h[src]-part of layer1         */
__device__ float g_mi[NN * HH];   /* segment sum of mij*eij        */
__device__ float g_tmp[NN * HH];  /* node MLP hidden               */
__device__ float g_dx[NN * 3];    /* segment sum of rel_x*xg       */

/* ---------------- small helpers ------------------------------------------ */
typedef unsigned long long u64t;
__device__ __forceinline__ u64t dup2(float v) {
    u64t r; asm("mov.b64 %0,{%1,%1};" : "=l"(r) : "f"(v)); return r;
}
__device__ __forceinline__ u64t pk2(float a, float b) {
    u64t r; asm("mov.b64 %0,{%1,%2};" : "=l"(r) : "f"(a), "f"(b)); return r;
}
__device__ __forceinline__ void fma2(u64t& d, u64t a, u64t b) {
    asm("fma.rn.f32x2 %0,%1,%2,%0;" : "+l"(d) : "l"(a), "l"(b));
}
__device__ __forceinline__ void unp2(u64t v, float& a, float& b) {
    asm("mov.b64 {%0,%1},%2;" : "=f"(a), "=f"(b) : "l"(v));
}
__device__ __forceinline__ void red4(float* p, float a, float b, float c, float d) {
    asm volatile("red.global.add.v4.f32 [%0], {%1,%2,%3,%4};"
                 :: "l"(p), "f"(a), "f"(b), "f"(c), "f"(d) : "memory");
}
__device__ __forceinline__ uint32_t smem_u32(const void* p) {
    uint32_t a;
    asm("{ .reg .u64 t; cvta.to.shared.u64 t, %1; cvt.u32.u64 %0, t; }"
        : "=r"(a) : "l"(p));
    return a;
}
/* pack (low half = a, high half = b) */
#define PACKBF2(res, a, b) \
    asm("cvt.rn.satfinite.bf16x2.f32 %0, %1, %2;" : "=r"(res) : "f"(b), "f"(a))
__device__ __forceinline__ void split2(float a0, float a1, uint32_t& hw, uint32_t& lw) {
    PACKBF2(hw, a0, a1);
    float h0 = __uint_as_float(hw << 16);
    float h1 = __uint_as_float(hw & 0xffff0000u);
    PACKBF2(lw, a0 - h0, a1 - h1);
}

/* ---------------- mma / ldmatrix ----------------------------------------- */
#define LDSM4(r, a) \
    asm volatile("ldmatrix.sync.aligned.m8n8.x4.shared.b16 {%0,%1,%2,%3},[%4];" \
        : "=r"((r)[0]), "=r"((r)[1]), "=r"((r)[2]), "=r"((r)[3]) : "r"(a))
#define MMA_B16(d, a, b0, b1) \
    asm volatile("mma.sync.aligned.m16n8k16.row.col.f32.bf16.bf16.f32 " \
        "{%0,%1,%2,%3},{%4,%5,%6,%7},{%8,%9},{%0,%1,%2,%3};" \
        : "+f"((d)[0]), "+f"((d)[1]), "+f"((d)[2]), "+f"((d)[3]) \
        : "r"((a)[0]), "r"((a)[1]), "r"((a)[2]), "r"((a)[3]), "r"(b0), "r"(b1))

/* XOR-swizzled bf16 tile: row r, 16B chunk c -> phys chunk (c&~7)|((c&7)^(r&7)) */
__device__ __forceinline__ uint32_t pch(int c, int r) {
    return (uint32_t)((c & ~7) | ((c & 7) ^ (r & 7)));
}

/* warp GEMM: D[16 rows x (16*NJP) cols] += A[16xK] * B[K x 16*NJP]^T */
template<int KSTEPS, bool X3, int CA, int CB, int NJP>
__device__ __forceinline__ void mma_gemm(const char* aH, const char* aL,
                                         const char* bH, const char* bL,
                                         float acc[][4], int wm, int wn, int lane) {
    int ar7 = lane & 7;
    int arow = 16 * wm + ((lane >> 3) & 1) * 8 + ar7;
    int acoff = lane >> 4;
    int brow_l = ((lane >> 4) & 1) * 8 + ar7;
    int bcoff = (lane >> 3) & 1;
    uint32_t aHb = smem_u32(aH) + (uint32_t)(arow * CA);
    uint32_t aLb = X3 ? (smem_u32(aL) + (uint32_t)(arow * CA)) : 0u;
    uint32_t bHb = smem_u32(bH);
    uint32_t bLb = X3 ? smem_u32(bL) : 0u;
#pragma unroll
    for (int ks = 0; ks < KSTEPS; ks++) {
        uint32_t aoff = pch(2 * ks + acoff, ar7) * 16;
        uint32_t ah[4], al[4];
        LDSM4(ah, aHb + aoff);
        if (X3) LDSM4(al, aLb + aoff);
        uint32_t boff = pch(2 * ks + bcoff, ar7) * 16;
#pragma unroll
        for (int jp = 0; jp < NJP; jp++) {
            uint32_t brb = (uint32_t)((wn * (16 * NJP) + jp * 16 + brow_l) * CB) + boff;
            uint32_t bh[4];
            LDSM4(bh, bHb + brb);
            MMA_B16(acc[2 * jp],     ah, bh[0], bh[1]);
            MMA_B16(acc[2 * jp + 1], ah, bh[2], bh[3]);
            if (X3) {
                uint32_t bl[4];
                LDSM4(bl, bLb + brb);
                MMA_B16(acc[2 * jp],     al, bh[0], bh[1]);
                MMA_B16(acc[2 * jp + 1], al, bh[2], bh[3]);
                MMA_B16(acc[2 * jp],     ah, bl[0], bl[1]);
                MMA_B16(acc[2 * jp + 1], ah, bl[2], bl[3]);
            }
        }
    }
}

/* stage D fragments -> fp32 smem [64][128], 16B-chunk swizzled (512B rows) */
template<int NJP>
__device__ __forceinline__ void stage_D(char* DS, const float acc[][4],
                                        int wm, int wn, int lane) {
    int r0 = 16 * wm + (lane >> 2);
    int r1 = r0 + 8;
    int cbase = wn * (16 * NJP) + 2 * (lane & 3);
#pragma unroll
    for (int j = 0; j < 2 * NJP; j++) {
        int cc = cbase + 8 * j;
        int ch = cc >> 2, inoff = (cc & 3) * 4;
        *(float2*)(DS + r0 * 512 + pch(ch, r0) * 16 + inoff) =
            make_float2(acc[j][0], acc[j][1]);
        *(float2*)(DS + r1 * 512 + pch(ch, r1) * 16 + inoff) =
            make_float2(acc[j][2], acc[j][3]);
    }
}

/* XOR-swizzled transposed activation layout (node kernels) */
__device__ __forceinline__ int sidx(int k, int r) {
    return (k * 16 + ((r >> 2) ^ ((k >> 2) & 15))) * 4 + (r & 3);
}
template<int KD>
__device__ __forceinline__ void gemm_acc_f2(const float* __restrict__ As,
                                            const float* __restrict__ Bs,
                                            float acc[4][4], int tr, int tc) {
    const float4* A4 = (const float4*)As;
    const float4* B4 = (const float4*)Bs;
    u64t a2[2][4];
#pragma unroll
    for (int j = 0; j < 4; j++) {
        a2[0][j] = pk2(acc[0][j], acc[1][j]);
        a2[1][j] = pk2(acc[2][j], acc[3][j]);
    }
#pragma unroll 4
    for (int k = 0; k < KD; k++) {
        ulonglong2 a = *(const ulonglong2*)(A4 + k * 16 + (tr ^ ((k >> 2) & 15)));
        float4 b = B4[k * 32 + tc];
        u64t b0 = dup2(b.x), b1 = dup2(b.y), b2 = dup2(b.z), b3 = dup2(b.w);
        fma2(a2[0][0], a.x, b0); fma2(a2[0][1], a.x, b1);
        fma2(a2[0][2], a.x, b2); fma2(a2[0][3], a.x, b3);
        fma2(a2[1][0], a.y, b0); fma2(a2[1][1], a.y, b1);
        fma2(a2[1][2], a.y, b2); fma2(a2[1][3], a.y, b3);
    }
#pragma unroll
    for (int j = 0; j < 4; j++) {
        unp2(a2[0][j], acc[0][j], acc[1][j]);
        unp2(a2[1][j], acc[2][j], acc[3][j]);
    }
}

/* ================= kernel A: per-node precompute + zero scratch (f32x2) == */
__global__ void __launch_bounds__(512, 1)
k_node_pre(const float* __restrict__ h, const float* __restrict__ ew1,
           const float* __restrict__ eb1) {
    float* sm = (float*)smraw;
    float* W1 = sm;
    float* W2 = W1 + 16384;
    float* As = W2 + 16384;
    int tid = threadIdx.x, tr = tid >> 5, tc = tid & 31;

    for (int i = tid; i < 16384; i += 512) {
        W1[i] = ew1[48 * 128 + i];
        W2[i] = ew1[176 * 128 + i];
    }
    int n0 = blockIdx.x * 64;
    for (int i = tid; i < 64 * 128; i += 512) {
        int r = i >> 7, k = i & 127, n = n0 + r;
        As[sidx(k, r)] = (n < NN) ? h[n * 128 + k] : 0.f;
    }
    for (int i = tid; i < 64 * 128; i += 512) {
        int n = n0 + (i >> 7);
        if (n < NN) g_mi[n * 128 + (i & 127)] = 0.f;
    }
    if (tid < 192) {
        int n = n0 + tid / 3;
        if (n < NN) g_dx[n * 3 + tid % 3] = 0.f;
    }
    __syncthreads();

    float a1[4][4], a2[4][4];
#pragma unroll
    for (int e = 0; e < 4; e++)
#pragma unroll
        for (int j = 0; j < 4; j++) { a1[e][j] = eb1[4 * tc + j]; a2[e][j] = 0.f; }
    gemm_acc_f2<128>(As, W1, a1, tr, tc);
    gemm_acc_f2<128>(As, W2, a2, tr, tc);
#pragma unroll
    for (int e = 0; e < 4; e++) {
        int n = n0 + tr * 4 + e;
        if (n < NN) {
            *(float4*)&g_g1[n * 128 + 4 * tc] =
                make_float4(a1[e][0], a1[e][1], a1[e][2], a1[e][3]);
            *(float4*)&g_g2[n * 128 + 4 * tc] =
                make_float4(a2[e][0], a2[e][1], a2[e][2], a2[e][3]);
        }
    }
}

/* ================= kernel B: mma.sync bf16 edge pipeline (512 thr) ======= */
#define SB_DST   0
#define SB_SRC   256
#define SB_RELX  512
#define SB_XL2   1280
#define SB_EB2   1536
#define SB_XB1   2048
#define SB_INFW  2560
#define SB_XW2   3072
#define SB_FEATH 4096
#define SB_FEATL 12288
#define SB_BUFM  4096
#define SB_TH    20480
#define SB_TL    36864
#define SB_DS    53248
#define SB_W1H   86016
#define SB_W1L   102400
#define SB_W2H   118784
#define SB_W2L   151552
#define SB_W3H   184320
#define SB_TOTAL 217088

__global__ void __launch_bounds__(512, 1)
k_edge(const float* __restrict__ x, const float* __restrict__ eattr,
       const float* __restrict__ ew1, const float* __restrict__ ew2,
       const float* __restrict__ eb2, const float* __restrict__ infw,
       const float* __restrict__ infb, const float* __restrict__ xw1,
       const float* __restrict__ xb1, const float* __restrict__ xw2,
       const float* __restrict__ xb2, const int* __restrict__ eidx) {
    char* sm = smraw;
    int* dsts = (int*)(sm + SB_DST);
    int* srcs = (int*)(sm + SB_SRC);
    float* relxs = (float*)(sm + SB_RELX);
    float* xl2s  = (float*)(sm + SB_XL2);
    float* eb2s  = (float*)(sm + SB_EB2);
    float* xb1s  = (float*)(sm + SB_XB1);
    float* infws = (float*)(sm + SB_INFW);
    float* xw2s  = (float*)(sm + SB_XW2);

    int tid = threadIdx.x;
    int lane = tid & 31;
    int wid = tid >> 5;                 /* 0..15 */
    int wm = wid >> 2, wn = wid & 3;    /* 4 x 4 warp grid, NJP=2 */
    int rg = wid, cg = lane;            /* epilogue: 4 edges x 4 cols per warp */

    for (int i = tid; i < 128 * 64; i += 512) {
        int n = i >> 6, k = i & 63;
        float v = (k < 48) ? ew1[k * 128 + n] : 0.f;
        __nv_bfloat16 hb = __float2bfloat16(v);
        uint32_t off = (uint32_t)(n * 128) + pch(k >> 3, n) * 16 + (k & 7) * 2;
        *(__nv_bfloat16*)(sm + SB_W1H + off) = hb;
        *(__nv_bfloat16*)(sm + SB_W1L + off) =
            __float2bfloat16(v - __bfloat162float(hb));
    }
    for (int i = tid; i < 128 * 128; i += 512) {
        int n = i >> 7, k = i & 127;
        uint32_t off = (uint32_t)(n * 256) + pch(k >> 3, n) * 16 + (k & 7) * 2;
        float v = ew2[k * 128 + n];
        __nv_bfloat16 hb = __float2bfloat16(v);
        *(__nv_bfloat16*)(sm + SB_W2H + off) = hb;
        *(__nv_bfloat16*)(sm + SB_W2L + off) =
            __float2bfloat16(v - __bfloat162float(hb));
        *(__nv_bfloat16*)(sm + SB_W3H + off) = __float2bfloat16(xw1[k * 128 + n]);
    }
    if (tid < 128) {
        eb2s[tid] = eb2[tid]; xb1s[tid] = xb1[tid];
        infws[tid] = infw[tid]; xw2s[tid] = xw2[tid];
    }
    __syncthreads();

    float eb2r[4], infwr[4], xb1r[4], xw2r[4];
#pragma unroll
    for (int j = 0; j < 4; j++) {
        eb2r[j] = eb2s[cg * 4 + j]; infwr[j] = infws[cg * 4 + j];
        xb1r[j] = xb1s[cg * 4 + j]; xw2r[j] = xw2s[cg * 4 + j];
    }
    const float infbv = infb[0];
    const float xb2v  = xb2[0];
    const float step  = 100.0f / 19.0f;
    const float coeff = -0.5f / (step * step);

    for (int tile = blockIdx.x; tile < NTILES_E; tile += gridDim.x) {
        __syncthreads();
        int e0 = tile * ETILE;

        if (tid < 64) {
            int e = e0 + tid;
            int d = eidx[e], s = eidx[EE + e];
            dsts[tid] = d; srcs[tid] = s;
            float rx = x[d * 3 + 0] - x[s * 3 + 0];
            float ry = x[d * 3 + 1] - x[s * 3 + 1];
            float rz = x[d * 3 + 2] - x[s * 3 + 2];
            relxs[tid * 3 + 0] = rx; relxs[tid * 3 + 1] = ry; relxs[tid * 3 + 2] = rz;
            xl2s[tid] = sqrtf(rx * rx + ry * ry + rz * rz);
        }
        for (int i = tid; i < 64 * 14; i += 512) {
            int e = i / 14, w = i - 14 * e;
            float2 t = *(const float2*)&eattr[(size_t)(e0 + e) * 28 + 2 * w];
            uint32_t hw, lw; split2(t.x, t.y, hw, lw);
            uint32_t off = (uint32_t)(e * 128) + pch(w >> 2, e) * 16 + (w & 3) * 4;
            *(uint32_t*)(sm + SB_FEATH + off) = hw;
            *(uint32_t*)(sm + SB_FEATL + off) = lw;
        }
        __syncthreads();

        for (int i = tid; i < 64 * 10; i += 512) {
            int e = i / 10, w = 14 + (i - 10 * e);
            int k0 = 2 * w - 28;
            float l2v = xl2s[e];
            float d0 = l2v - (float)k0 * step, d1 = l2v - (float)(k0 + 1) * step;
            uint32_t hw, lw;
            split2(expf(coeff * d0 * d0), expf(coeff * d1 * d1), hw, lw);
            uint32_t off = (uint32_t)(e * 128) + pch(w >> 2, e) * 16 + (w & 3) * 4;
            *(uint32_t*)(sm + SB_FEATH + off) = hw;
            *(uint32_t*)(sm + SB_FEATL + off) = lw;
        }
        int dr[4], sr[4];
#pragma unroll
        for (int i = 0; i < 4; i++) { dr[i] = dsts[rg * 4 + i]; sr[i] = srcs[rg * 4 + i]; }
        __syncthreads();

        /* ---- GEMM1 (K=48, bf16x3): D = feat @ W1 ---- */
        float acc[4][4];
#pragma unroll
        for (int j = 0; j < 4; j++)
#pragma unroll
            for (int q = 0; q < 4; q++) acc[j][q] = 0.f;
        mma_gemm<3, true, 128, 128, 2>(sm + SB_FEATH, sm + SB_FEATL,
                                       sm + SB_W1H, sm + SB_W1L, acc, wm, wn, lane);
        stage_D<2>(sm + SB_DS, acc, wm, wn, lane);
        __syncthreads();

        /* ---- ep1: t1 = relu(D + g1[dst] + g2[src]) -> TH/TL ---- */
#pragma unroll
        for (int i = 0; i < 4; i++) {
            int e = rg * 4 + i;
            float4 dv = *(const float4*)(sm + SB_DS + e * 512 + pch(cg, e) * 16);
            float4 a = *(const float4*)&g_g1[(size_t)dr[i] * 128 + cg * 4];
            float4 b = *(const float4*)&g_g2[(size_t)sr[i] * 128 + cg * 4];
            float v0 = fmaxf(dv.x + a.x + b.x, 0.f);
            float v1 = fmaxf(dv.y + a.y + b.y, 0.f);
            float v2 = fmaxf(dv.z + a.z + b.z, 0.f);
            float v3 = fmaxf(dv.w + a.w + b.w, 0.f);
            uint32_t h0, l0, h1, l1;
            split2(v0, v1, h0, l0); split2(v2, v3, h1, l1);
            uint32_t off = (uint32_t)(e * 256) + pch(cg >> 1, e) * 16 + (cg & 1) * 8;
            *(uint2*)(sm + SB_TH + off) = make_uint2(h0, h1);
            *(uint2*)(sm + SB_TL + off) = make_uint2(l0, l1);
        }
        __syncthreads();

        /* ---- GEMM2 (K=128, bf16x3): D = t1 @ W2 ---- */
#pragma unroll
        for (int j = 0; j < 4; j++)
#pragma unroll
            for (int q = 0; q < 4; q++) acc[j][q] = 0.f;
        mma_gemm<8, true, 256, 256, 2>(sm + SB_TH, sm + SB_TL,
                                       sm + SB_W2H, sm + SB_W2L, acc, wm, wn, lane);
        stage_D<2>(sm + SB_DS, acc, wm, wn, lane);
        __syncthreads();

        /* ---- ep2: mij = relu(D+eb2); gate; scatter mi; bufM ---- */
        float pd[4];
        float mv[4][4];
#pragma unroll
        for (int i = 0; i < 4; i++) {
            int e = rg * 4 + i;
            float4 dv = *(const float4*)(sm + SB_DS + e * 512 + pch(cg, e) * 16);
            float m0 = fmaxf(dv.x + eb2r[0], 0.f);
            float m1 = fmaxf(dv.y + eb2r[1], 0.f);
            float m2 = fmaxf(dv.z + eb2r[2], 0.f);
            float m3 = fmaxf(dv.w + eb2r[3], 0.f);
            mv[i][0] = m0; mv[i][1] = m1; mv[i][2] = m2; mv[i][3] = m3;
            pd[i] = m0 * infwr[0] + m1 * infwr[1] + m2 * infwr[2] + m3 * infwr[3];
            uint32_t w0, w1;
            PACKBF2(w0, m0, m1); PACKBF2(w1, m2, m3);
            uint32_t off = (uint32_t)(e * 256) + pch(cg >> 1, e) * 16 + (cg & 1) * 8;
            *(uint2*)(sm + SB_BUFM + off) = make_uint2(w0, w1);
        }
#pragma unroll
        for (int o = 16; o > 0; o >>= 1)
#pragma unroll
            for (int i = 0; i < 4; i++)
                pd[i] += __shfl_xor_sync(0xffffffffu, pd[i], o);
#pragma unroll
        for (int i = 0; i < 4; i++) {
            float eij = 1.f / (1.f + expf(-(pd[i] + infbv)));
            red4(&g_mi[(size_t)dr[i] * 128 + cg * 4],
                 mv[i][0] * eij, mv[i][1] * eij, mv[i][2] * eij, mv[i][3] * eij);
        }
        __syncthreads();

        /* ---- GEMM3 (K=128, bf16 x1): D = mij @ xw1 ---- */
#pragma unroll
        for (int j = 0; j < 4; j++)
#pragma unroll
            for (int q = 0; q < 4; q++) acc[j][q] = 0.f;
        mma_gemm<8, false, 256, 256, 2>(sm + SB_BUFM, 0,
                                        sm + SB_W3H, 0, acc, wm, wn, lane);
        stage_D<2>(sm + SB_DS, acc, wm, wn, lane);
        __syncthreads();

        /* ---- ep3: xg = relu(D+xb1).xw2 + xb2 ; scatter dx ---- */
        float q[4];
#pragma unroll
        for (int i = 0; i < 4; i++) {
            int e = rg * 4 + i;
            float4 dv = *(const float4*)(sm + SB_DS + e * 512 + pch(cg, e) * 16);
            q[i] = fmaxf(dv.x + xb1r[0], 0.f) * xw2r[0]
                 + fmaxf(dv.y + xb1r[1], 0.f) * xw2r[1]
                 + fmaxf(dv.z + xb1r[2], 0.f) * xw2r[2]
                 + fmaxf(dv.w + xb1r[3], 0.f) * xw2r[3];
        }
#pragma unroll
        for (int o = 16; o > 0; o >>= 1)
#pragma unroll
            for (int i = 0; i < 4; i++)
                q[i] += __shfl_xor_sync(0xffffffffu, q[i], o);
        if (cg < 3) {
#pragma unroll
            for (int i = 0; i < 4; i++) {
                float xg = q[i] + xb2v;
                atomicAdd(&g_dx[dr[i] * 3 + cg],
                          relxs[(rg * 4 + i) * 3 + cg] * xg);
            }
        }
    }
}

/* ================= kernel C1: hidden = relu([mi,h]@nw1+nb1) (f32x2) ====== */
__global__ void __launch_bounds__(512, 1)
k_node1(const float* __restrict__ h, const float* __restrict__ nw1,
        const float* __restrict__ nb1) {
    float* sm = (float*)smraw;
    float* W  = sm;
    float* As = W + 32768;
    int tid = threadIdx.x, tr = tid >> 5, tc = tid & 31;

    for (int i = tid; i < 32768; i += 512) W[i] = nw1[i];
    int n0 = blockIdx.x * 64;
    for (int i = tid; i < 64 * 256; i += 512) {
        int r = i >> 8, k = i & 255, n = n0 + r;
        float v = 0.f;
        if (n < NN) v = (k < 128) ? g_mi[n * 128 + k] : h[n * 128 + (k - 128)];
        As[sidx(k, r)] = v;
    }
    __syncthreads();

    float acc[4][4];
#pragma unroll
    for (int e = 0; e < 4; e++)
#pragma unroll
        for (int j = 0; j < 4; j++) acc[e][j] = nb1[4 * tc + j];
    gemm_acc_f2<256>(As, W, acc, tr, tc);
#pragma unroll
    for (int e = 0; e < 4; e++) {
        int n = n0 + tr * 4 + e;
        if (n < NN)
            *(float4*)&g_tmp[n * 128 + 4 * tc] =
                make_float4(fmaxf(acc[e][0], 0.f), fmaxf(acc[e][1], 0.f),
                            fmaxf(acc[e][2], 0.f), fmaxf(acc[e][3], 0.f));
    }
}

/* ================= kernel C2: out = hidden@nw2+nb2 (f32x2) =============== */
__global__ void __launch_bounds__(512, 1)
k_node2(const float* __restrict__ nw2, const float* __restrict__ nb2,
        float* __restrict__ out) {
    float* sm = (float*)smraw;
    float* W  = sm;
    float* As = W + 16384;
    int tid = threadIdx.x, tr = tid >> 5, tc = tid & 31;

    for (int i = tid; i < 16384; i += 512) W[i] = nw2[i];
    int n0 = blockIdx.x * 64;
    for (int i = tid; i < 64 * 128; i += 512) {
        int r = i >> 7, k = i & 127, n = n0 + r;
        As[sidx(k, r)] = (n < NN) ? g_tmp[n * 128 + k] : 0.f;
    }
    __syncthreads();

    float acc[4][4];
#pragma unroll
    for (int e = 0; e < 4; e++)
#pragma unroll
        for (int j = 0; j < 4; j++) acc[e][j] = nb2[4 * tc + j];
    gemm_acc_f2<128>(As, W, acc, tr, tc);
#pragma unroll
    for (int e = 0; e < 4; e++) {
        int n = n0 + tr * 4 + e;
        if (n < NN)
            *(float4*)&out[n * 128 + 4 * tc] =
                make_float4(acc[e][0], acc[e][1], acc[e][2], acc[e][3]);
    }
}

/* ================= kernel X: x_out = x + dx/E ============================ */
__global__ void k_xupd(const float* __restrict__ x, float* __restrict__ out) {
    int i = blockIdx.x * blockDim.x + threadIdx.x;
    if (i < NN * 3)
        out[NN * 128 + i] = x[i] + g_dx[i] * (1.0f / (float)EE);
}

/* ========================================================================= */
extern "C" void kernel_launch(void* const* d_in, const int* in_sizes, int n_in,
                              void* d_out, int out_size) {
    const float* h    = (const float*)d_in[0];
    const float* x    = (const float*)d_in[1];
    const float* ea   = (const float*)d_in[2];
    const float* ew1  = (const float*)d_in[3];
    const float* eb1  = (const float*)d_in[4];
    const float* ew2  = (const float*)d_in[5];
    const float* eb2  = (const float*)d_in[6];
    const float* infw = (const float*)d_in[7];
    const float* infb = (const float*)d_in[8];
    const float* nw1  = (const float*)d_in[9];
    const float* nb1  = (const float*)d_in[10];
    const float* nw2  = (const float*)d_in[11];
    const float* nb2  = (const float*)d_in[12];
    const float* xw1  = (const float*)d_in[13];
    const float* xb1  = (const float*)d_in[14];
    const float* xw2  = (const float*)d_in[15];
    const float* xb2  = (const float*)d_in[16];
    const int*   ei   = (const int*)d_in[17];
    float* out = (float*)d_out;

    const size_t smA  = (16384 + 16384 + 8192) * sizeof(float);   /* 163840 */
    const size_t smC1 = (32768 + 16384) * sizeof(float);          /* 196608 */
    const size_t smC2 = (16384 + 8192) * sizeof(float);           /*  98304 */

    cudaFuncSetAttribute(k_node_pre, cudaFuncAttributeMaxDynamicSharedMemorySize, (int)smA);
    cudaFuncSetAttribute(k_edge,     cudaFuncAttributeMaxDynamicSharedMemorySize, SB_TOTAL);
    cudaFuncSetAttribute(k_node1,    cudaFuncAttributeMaxDynamicSharedMemorySize, (int)smC1);
    cudaFuncSetAttribute(k_node2,    cudaFuncAttributeMaxDynamicSharedMemorySize, (int)smC2);

    k_node_pre<<<NTILES_N, 512, smA>>>(h, ew1, eb1);
    k_edge<<<148, 512, SB_TOTAL>>>(x, ea, ew1, ew2, eb2, infw, infb,
                                   xw1, xb1, xw2, xb2, ei);
    k_node1<<<NTILES_N, 512, smC1>>>(h, nw1, nb1);
    k_node2<<<NTILES_N, 512, smC2>>>(nw2, nb2, out);
    k_xupd<<<(NN * 3 + 255) / 256, 256>>>(x, out);
}

// round 12
// speedup vs baseline: 1.1563x; 1.0407x over previous
#include <cuda_runtime.h>
#include <cuda_bf16.h>
#include <math.h>
#include <stdint.h>

#define NN 20000
#define EE 320000
#define HH 128
#define NTILES_N ((NN + 63) / 64)   /* 313 */
#define ETILE 128
#define NTILES_E (EE / ETILE)       /* 2500 */

extern __shared__ char smraw[];

/* ---------------- scratch (static device globals; no allocations) -------- */
__device__ float g_g1[NN * HH];   /* h[dst]-part of layer1 (+eb1)  */
__device__ float g_g2[NN * HH];   /* h[src]-part of layer1         */
__device__ float g_mi[NN * HH];   /* segment sum of mij*eij        */
__device__ float g_tmp[NN * HH];  /* node MLP hidden               */
__device__ float g_dx[NN * 3];    /* segment sum of rel_x*xg       */

/* ---------------- small helpers ------------------------------------------ */
typedef unsigned long long u64t;
__device__ __forceinline__ u64t dup2(float v) {
    u64t r; asm("mov.b64 %0,{%1,%1};" : "=l"(r) : "f"(v)); return r;
}
__device__ __forceinline__ u64t pk2(float a, float b) {
    u64t r; asm("mov.b64 %0,{%1,%2};" : "=l"(r) : "f"(a), "f"(b)); return r;
}
__device__ __forceinline__ void fma2(u64t& d, u64t a, u64t b) {
    asm("fma.rn.f32x2 %0,%1,%2,%0;" : "+l"(d) : "l"(a), "l"(b));
}
__device__ __forceinline__ void unp2(u64t v, float& a, float& b) {
    asm("mov.b64 {%0,%1},%2;" : "=f"(a), "=f"(b) : "l"(v));
}
__device__ __forceinline__ void red2(float* p, float a, float b) {
    asm volatile("red.global.add.v2.f32 [%0], {%1,%2};"
                 :: "l"(p), "f"(a), "f"(b) : "memory");
}
__device__ __forceinline__ uint32_t smem_u32(const void* p) {
    uint32_t a;
    asm("{ .reg .u64 t; cvta.to.shared.u64 t, %1; cvt.u32.u64 %0, t; }"
        : "=r"(a) : "l"(p));
    return a;
}
/* pack (low half = a, high half = b) */
#define PACKBF2(res, a, b) \
    asm("cvt.rn.satfinite.bf16x2.f32 %0, %1, %2;" : "=r"(res) : "f"(b), "f"(a))
__device__ __forceinline__ void split2(float a0, float a1, uint32_t& hw, uint32_t& lw) {
    PACKBF2(hw, a0, a1);
    float h0 = __uint_as_float(hw << 16);
    float h1 = __uint_as_float(hw & 0xffff0000u);
    PACKBF2(lw, a0 - h0, a1 - h1);
}

/* ---------------- mma / ldmatrix ----------------------------------------- */
#define LDSM4(r, a) \
    asm volatile("ldmatrix.sync.aligned.m8n8.x4.shared.b16 {%0,%1,%2,%3},[%4];" \
        : "=r"((r)[0]), "=r"((r)[1]), "=r"((r)[2]), "=r"((r)[3]) : "r"(a))
#define MMA_B16(d, a, b0, b1) \
    asm volatile("mma.sync.aligned.m16n8k16.row.col.f32.bf16.bf16.f32 " \
        "{%0,%1,%2,%3},{%4,%5,%6,%7},{%8,%9},{%0,%1,%2,%3};" \
        : "+f"((d)[0]), "+f"((d)[1]), "+f"((d)[2]), "+f"((d)[3]) \
        : "r"((a)[0]), "r"((a)[1]), "r"((a)[2]), "r"((a)[3]), "r"(b0), "r"(b1))

/* XOR-swizzled bf16 tile: row r, 16B chunk c -> phys chunk (c&~7)|((c&7)^(r&7)) */
__device__ __forceinline__ uint32_t pch(int c, int r) {
    return (uint32_t)((c & ~7) | ((c & 7) ^ (r & 7)));
}

/* warp GEMM: D[16*MBLK rows x 16*NJP cols] += A * B^T, acc[MBLK*2*NJP][4] */
template<int KSTEPS, bool X3, int CA, int CB, int MBLK, int NJP>
__device__ __forceinline__ void mma_gemm(const char* aH, const char* aL,
                                         const char* bH, const char* bL,
                                         float acc[][4], int wm, int wn, int lane) {
    int ar7 = lane & 7;
    int arow_in = ((lane >> 3) & 1) * 8 + ar7;
    int acoff = lane >> 4;
    int brow_l = ((lane >> 4) & 1) * 8 + ar7;
    int bcoff = (lane >> 3) & 1;
    uint32_t aHb = smem_u32(aH);
    uint32_t aLb = X3 ? smem_u32(aL) : 0u;
    uint32_t bHb = smem_u32(bH);
    uint32_t bLb = X3 ? smem_u32(bL) : 0u;
#pragma unroll
    for (int ks = 0; ks < KSTEPS; ks++) {
        uint32_t ah[MBLK][4], al[MBLK][4];
        uint32_t achoff = pch(2 * ks + acoff, ar7) * 16;
#pragma unroll
        for (int mb = 0; mb < MBLK; mb++) {
            int arow = 16 * MBLK * wm + 16 * mb + arow_in;
            LDSM4(ah[mb], aHb + (uint32_t)(arow * CA) + achoff);
            if (X3) LDSM4(al[mb], aLb + (uint32_t)(arow * CA) + achoff);
        }
        uint32_t boff = pch(2 * ks + bcoff, ar7) * 16;
#pragma unroll
        for (int jp = 0; jp < NJP; jp++) {
            uint32_t brb = (uint32_t)((wn * (16 * NJP) + jp * 16 + brow_l) * CB) + boff;
            uint32_t bh[4], bl[4];
            LDSM4(bh, bHb + brb);
            if (X3) LDSM4(bl, bLb + brb);
#pragma unroll
            for (int mb = 0; mb < MBLK; mb++) {
                float* a0 = acc[mb * 2 * NJP + 2 * jp];
                float* a1 = acc[mb * 2 * NJP + 2 * jp + 1];
                MMA_B16(a0, ah[mb], bh[0], bh[1]);
                MMA_B16(a1, ah[mb], bh[2], bh[3]);
                if (X3) {
                    MMA_B16(a0, al[mb], bh[0], bh[1]);
                    MMA_B16(a1, al[mb], bh[2], bh[3]);
                    MMA_B16(a0, ah[mb], bl[0], bl[1]);
                    MMA_B16(a1, ah[mb], bl[2], bl[3]);
                }
            }
        }
    }
}

/* XOR-swizzled transposed activation layout (node kernels) */
__device__ __forceinline__ int sidx(int k, int r) {
    return (k * 16 + ((r >> 2) ^ ((k >> 2) & 15))) * 4 + (r & 3);
}
template<int KD>
__device__ __forceinline__ void gemm_acc_f2(const float* __restrict__ As,
                                            const float* __restrict__ Bs,
                                            float acc[4][4], int tr, int tc) {
    const float4* A4 = (const float4*)As;
    const float4* B4 = (const float4*)Bs;
    u64t a2[2][4];
#pragma unroll
    for (int j = 0; j < 4; j++) {
        a2[0][j] = pk2(acc[0][j], acc[1][j]);
        a2[1][j] = pk2(acc[2][j], acc[3][j]);
    }
#pragma unroll 4
    for (int k = 0; k < KD; k++) {
        ulonglong2 a = *(const ulonglong2*)(A4 + k * 16 + (tr ^ ((k >> 2) & 15)));
        float4 b = B4[k * 32 + tc];
        u64t b0 = dup2(b.x), b1 = dup2(b.y), b2 = dup2(b.z), b3 = dup2(b.w);
        fma2(a2[0][0], a.x, b0); fma2(a2[0][1], a.x, b1);
        fma2(a2[0][2], a.x, b2); fma2(a2[0][3], a.x, b3);
        fma2(a2[1][0], a.y, b0); fma2(a2[1][1], a.y, b1);
        fma2(a2[1][2], a.y, b2); fma2(a2[1][3], a.y, b3);
    }
#pragma unroll
    for (int j = 0; j < 4; j++) {
        unp2(a2[0][j], acc[0][j], acc[1][j]);
        unp2(a2[1][j], acc[2][j], acc[3][j]);
    }
}
__device__ __forceinline__ void red4(float* p, float a, float b, float c, float d) {
    asm volatile("red.global.add.v4.f32 [%0], {%1,%2,%3,%4};"
                 :: "l"(p), "f"(a), "f"(b), "f"(c), "f"(d) : "memory");
}

/* ================= kernel A: per-node precompute + zero scratch (f32x2) == */
__global__ void __launch_bounds__(512, 1)
k_node_pre(const float* __restrict__ h, const float* __restrict__ ew1,
           const float* __restrict__ eb1) {
    float* sm = (float*)smraw;
    float* W1 = sm;
    float* W2 = W1 + 16384;
    float* As = W2 + 16384;
    int tid = threadIdx.x, tr = tid >> 5, tc = tid & 31;

    for (int i = tid; i < 16384; i += 512) {
        W1[i] = ew1[48 * 128 + i];
        W2[i] = ew1[176 * 128 + i];
    }
    int n0 = blockIdx.x * 64;
    for (int i = tid; i < 64 * 128; i += 512) {
        int r = i >> 7, k = i & 127, n = n0 + r;
        As[sidx(k, r)] = (n < NN) ? h[n * 128 + k] : 0.f;
    }
    for (int i = tid; i < 64 * 128; i += 512) {
        int n = n0 + (i >> 7);
        if (n < NN) g_mi[n * 128 + (i & 127)] = 0.f;
    }
    if (tid < 192) {
        int n = n0 + tid / 3;
        if (n < NN) g_dx[n * 3 + tid % 3] = 0.f;
    }
    __syncthreads();

    float a1[4][4], a2[4][4];
#pragma unroll
    for (int e = 0; e < 4; e++)
#pragma unroll
        for (int j = 0; j < 4; j++) { a1[e][j] = eb1[4 * tc + j]; a2[e][j] = 0.f; }
    gemm_acc_f2<128>(As, W1, a1, tr, tc);
    gemm_acc_f2<128>(As, W2, a2, tr, tc);
#pragma unroll
    for (int e = 0; e < 4; e++) {
        int n = n0 + tr * 4 + e;
        if (n < NN) {
            *(float4*)&g_g1[n * 128 + 4 * tc] =
                make_float4(a1[e][0], a1[e][1], a1[e][2], a1[e][3]);
            *(float4*)&g_g2[n * 128 + 4 * tc] =
                make_float4(a2[e][0], a2[e][1], a2[e][2], a2[e][3]);
        }
    }
}

/* ================= kernel B: edge pipeline, fragment-direct epilogues ==== */
/* smem byte offsets (total 231936 <= 232448) */
#define SB_DST   0        /* 512   */
#define SB_PDB   512      /* 2048  : [128 rows][4 wn] f32 */
#define SB_FEATH 2560     /* 16384 : [128][128B]  (BUFM overlays both feat) */
#define SB_FEATL 18944    /* 16384 */
#define SB_BUFM  2560     /* 32768 : [128][256B] bf16 mij */
#define SB_TH    35328    /* 32768 : [128][256B] */
#define SB_TL    68096    /* 32768 */
#define SB_W1H   100864   /* 16384 : [128][128B] */
#define SB_W1L   117248   /* 16384 */
#define SB_W2H   133632   /* 32768 : [128][256B] */
#define SB_W2L   166400   /* 32768 */
#define SB_W3    199168   /* 32768 */
#define SB_TOTAL 231936

__global__ void __launch_bounds__(512, 1)
k_edge(const float* __restrict__ x, const float* __restrict__ eattr,
       const float* __restrict__ ew1, const float* __restrict__ ew2,
       const float* __restrict__ eb2, const float* __restrict__ infw,
       const float* __restrict__ infb, const float* __restrict__ xw1,
       const float* __restrict__ xb1, const float* __restrict__ xw2,
       const float* __restrict__ xb2, const int* __restrict__ eidx) {
    char* sm = smraw;
    int* dsts = (int*)(sm + SB_DST);
    float* pdb = (float*)(sm + SB_PDB);

    int tid = threadIdx.x;
    int lane = tid & 31;
    int wid = tid >> 5;                 /* 0..15 */
    int wm = wid >> 2, wn = wid & 3;    /* 4x4 warp grid, warp tile 32x32 */

    /* ---- one-time weights -> swizzled bf16 tiles ---- */
    for (int i = tid; i < 128 * 64; i += 512) {
        int n = i >> 6, k = i & 63;
        float v = (k < 48) ? ew1[k * 128 + n] : 0.f;
        __nv_bfloat16 hb = __float2bfloat16(v);
        uint32_t off = (uint32_t)(n * 128) + pch(k >> 3, n) * 16 + (k & 7) * 2;
        *(__nv_bfloat16*)(sm + SB_W1H + off) = hb;
        *(__nv_bfloat16*)(sm + SB_W1L + off) =
            __float2bfloat16(v - __bfloat162float(hb));
    }
    for (int i = tid; i < 128 * 128; i += 512) {
        int n = i >> 7, k = i & 127;
        uint32_t off = (uint32_t)(n * 256) + pch(k >> 3, n) * 16 + (k & 7) * 2;
        float v = ew2[k * 128 + n];
        __nv_bfloat16 hb = __float2bfloat16(v);
        *(__nv_bfloat16*)(sm + SB_W2H + off) = hb;
        *(__nv_bfloat16*)(sm + SB_W2L + off) =
            __float2bfloat16(v - __bfloat162float(hb));
        *(__nv_bfloat16*)(sm + SB_W3 + off) = __float2bfloat16(xw1[k * 128 + n]);
    }
    __syncthreads();

    const float infbv = infb[0];
    const float xb2v  = xb2[0];
    const float step  = 100.0f / 19.0f;
    const float coeff = -0.5f / (step * step);

    /* this thread's fragment rows (q = mb*2 + half): row = 32wm+16mb+(lane>>2)+8*half */
    int rowq[4];
#pragma unroll
    for (int q = 0; q < 4; q++)
        rowq[q] = 32 * wm + 16 * (q >> 1) + (lane >> 2) + 8 * (q & 1);

    for (int tile = blockIdx.x; tile < NTILES_E; tile += gridDim.x) {
        __syncthreads();                      /* s0 */
        int e0 = tile * ETILE;

        /* ---- build: idx/rbf (tid<128) + attr (all) ---- */
        if (tid < 128) {
            int e = e0 + tid;
            int d = __ldg(&eidx[e]), s = __ldg(&eidx[EE + e]);
            dsts[tid] = d;
            float rx = x[d * 3 + 0] - x[s * 3 + 0];
            float ry = x[d * 3 + 1] - x[s * 3 + 1];
            float rz = x[d * 3 + 2] - x[s * 3 + 2];
            float l2 = sqrtf(rx * rx + ry * ry + rz * rz);
#pragma unroll
            for (int kk = 0; kk < 10; kk++) {
                int w = 14 + kk;
                float d0 = l2 - (float)(2 * kk) * step;
                float d1 = l2 - (float)(2 * kk + 1) * step;
                uint32_t hw, lw;
                split2(expf(coeff * d0 * d0), expf(coeff * d1 * d1), hw, lw);
                uint32_t off = (uint32_t)(tid * 128) + pch(w >> 2, tid) * 16 + (w & 3) * 4;
                *(uint32_t*)(sm + SB_FEATH + off) = hw;
                *(uint32_t*)(sm + SB_FEATL + off) = lw;
            }
        }
        for (int i = tid; i < 128 * 14; i += 512) {
            int e = i / 14, w = i - 14 * e;
            float2 t = *(const float2*)&eattr[(size_t)(e0 + e) * 28 + 2 * w];
            uint32_t hw, lw; split2(t.x, t.y, hw, lw);
            uint32_t off = (uint32_t)(e * 128) + pch(w >> 2, e) * 16 + (w & 3) * 4;
            *(uint32_t*)(sm + SB_FEATH + off) = hw;
            *(uint32_t*)(sm + SB_FEATL + off) = lw;
        }
        __syncthreads();                      /* s2: feat + dsts ready */

        /* prefetch per-row indices (hidden by GEMM1) */
        int dR[4], sR[4];
#pragma unroll
        for (int q = 0; q < 4; q++) {
            dR[q] = dsts[rowq[q]];
            sR[q] = __ldg(&eidx[EE + e0 + rowq[q]]);
        }

        /* ---- GEMM1 (K=48, bf16x3): D = feat @ W1 ---- */
        float acc[8][4];
#pragma unroll
        for (int j = 0; j < 8; j++)
#pragma unroll
            for (int q = 0; q < 4; q++) acc[j][q] = 0.f;
        mma_gemm<3, true, 128, 128, 2, 2>(sm + SB_FEATH, sm + SB_FEATL,
                                          sm + SB_W1H, sm + SB_W1L, acc, wm, wn, lane);

        /* ---- ep1 (fragment-direct): t1 = relu(D + g1[d] + g2[s]) -> TH/TL */
#pragma unroll
        for (int q = 0; q < 4; q++) {
            const float* g1p = g_g1 + (size_t)dR[q] * 128;
            const float* g2p = g_g2 + (size_t)sR[q] * 128;
            int row = rowq[q];
            int e01 = (q & 1) * 2;
#pragma unroll
            for (int j = 0; j < 4; j++) {
                int col = 32 * wn + 8 * j + 2 * (lane & 3);
                float2 a = *(const float2*)(g1p + col);
                float2 b = *(const float2*)(g2p + col);
                float* ac = acc[(q >> 1) * 4 + j];
                float v0 = fmaxf(ac[e01] + a.x + b.x, 0.f);
                float v1 = fmaxf(ac[e01 + 1] + a.y + b.y, 0.f);
                uint32_t hw, lw; split2(v0, v1, hw, lw);
                uint32_t off = (uint32_t)(row * 256) + pch(col >> 3, row) * 16 + (col & 7) * 2;
                *(uint32_t*)(sm + SB_TH + off) = hw;
                *(uint32_t*)(sm + SB_TL + off) = lw;
            }
        }
        __syncthreads();                      /* s_T */

        /* ---- GEMM2 (K=128, bf16x3): D = t1 @ W2 ---- */
#pragma unroll
        for (int j = 0; j < 8; j++)
#pragma unroll
            for (int q = 0; q < 4; q++) acc[j][q] = 0.f;
        mma_gemm<8, true, 256, 256, 2, 2>(sm + SB_TH, sm + SB_TL,
                                          sm + SB_W2H, sm + SB_W2L, acc, wm, wn, lane);

        /* ---- ep2a: mij = relu(D+eb2) in place; gate partials; bufM ---- */
        float pdv[4] = {0.f, 0.f, 0.f, 0.f};
#pragma unroll
        for (int j = 0; j < 4; j++) {
            int col = 32 * wn + 8 * j + 2 * (lane & 3);
            float2 be = __ldg((const float2*)(eb2 + col));
            float2 iw = __ldg((const float2*)(infw + col));
#pragma unroll
            for (int q = 0; q < 4; q++) {
                float* ac = acc[(q >> 1) * 4 + j];
                int e01 = (q & 1) * 2;
                float m0 = fmaxf(ac[e01] + be.x, 0.f);
                float m1 = fmaxf(ac[e01 + 1] + be.y, 0.f);
                ac[e01] = m0; ac[e01 + 1] = m1;
                pdv[q] += m0 * iw.x + m1 * iw.y;
                uint32_t w; PACKBF2(w, m0, m1);
                int row = rowq[q];
                uint32_t off = (uint32_t)(row * 256) + pch(col >> 3, row) * 16 + (col & 7) * 2;
                *(uint32_t*)(sm + SB_BUFM + off) = w;
            }
        }
#pragma unroll
        for (int o = 1; o <= 2; o <<= 1)
#pragma unroll
            for (int q = 0; q < 4; q++)
                pdv[q] += __shfl_xor_sync(0xffffffffu, pdv[q], o);
        if ((lane & 3) == 0) {
#pragma unroll
            for (int q = 0; q < 4; q++)
                pdb[rowq[q] * 4 + wn] = pdv[q];
        }
        __syncthreads();                      /* s_pd: pdb + bufM ready */

        /* ---- ep2b: eij; scatter mi (red2 from fragments) ---- */
#pragma unroll
        for (int q = 0; q < 4; q++) {
            float4 p = *(const float4*)(pdb + rowq[q] * 4);
            float eij = 1.f / (1.f + expf(-(p.x + p.y + p.z + p.w + infbv)));
            float* mip = g_mi + (size_t)dR[q] * 128;
            int e01 = (q & 1) * 2;
#pragma unroll
            for (int j = 0; j < 4; j++) {
                int col = 32 * wn + 8 * j + 2 * (lane & 3);
                float* ac = acc[(q >> 1) * 4 + j];
                red2(mip + col, ac[e01] * eij, ac[e01 + 1] * eij);
            }
        }

        /* ---- GEMM3 (K=128, bf16 x1): D = mij @ xw1 ---- */
#pragma unroll
        for (int j = 0; j < 8; j++)
#pragma unroll
            for (int q = 0; q < 4; q++) acc[j][q] = 0.f;
        mma_gemm<8, false, 256, 256, 2, 2>(sm + SB_BUFM, 0,
                                           sm + SB_W3, 0, acc, wm, wn, lane);
        __syncthreads();                      /* s_pdsafe: pdb reads done */

        /* ---- ep3a: xg partials ---- */
        float qv[4] = {0.f, 0.f, 0.f, 0.f};
#pragma unroll
        for (int j = 0; j < 4; j++) {
            int col = 32 * wn + 8 * j + 2 * (lane & 3);
            float2 xb = __ldg((const float2*)(xb1 + col));
            float2 xw = __ldg((const float2*)(xw2 + col));
#pragma unroll
            for (int q = 0; q < 4; q++) {
                float* ac = acc[(q >> 1) * 4 + j];
                int e01 = (q & 1) * 2;
                qv[q] += fmaxf(ac[e01] + xb.x, 0.f) * xw.x
                       + fmaxf(ac[e01 + 1] + xb.y, 0.f) * xw.y;
            }
        }
#pragma unroll
        for (int o = 1; o <= 2; o <<= 1)
#pragma unroll
            for (int q = 0; q < 4; q++)
                qv[q] += __shfl_xor_sync(0xffffffffu, qv[q], o);
        if ((lane & 3) == 0) {
#pragma unroll
            for (int q = 0; q < 4; q++)
                pdb[rowq[q] * 4 + wn] = qv[q];
        }
        __syncthreads();                      /* s_xg */

        /* ---- ep3b: xg; scatter dx (wn==0 warps, quad leaders) ---- */
        if (wn == 0 && (lane & 3) == 0) {
#pragma unroll
            for (int q = 0; q < 4; q++) {
                float4 p = *(const float4*)(pdb + rowq[q] * 4);
                float xg = p.x + p.y + p.z + p.w + xb2v;
                int d = dR[q], s = sR[q];
                float rx = __ldg(&x[d * 3 + 0]) - __ldg(&x[s * 3 + 0]);
                float ry = __ldg(&x[d * 3 + 1]) - __ldg(&x[s * 3 + 1]);
                float rz = __ldg(&x[d * 3 + 2]) - __ldg(&x[s * 3 + 2]);
                atomicAdd(&g_dx[d * 3 + 0], rx * xg);
                atomicAdd(&g_dx[d * 3 + 1], ry * xg);
                atomicAdd(&g_dx[d * 3 + 2], rz * xg);
            }
        }
    }
}

/* ================= kernel C1: hidden = relu([mi,h]@nw1+nb1) (f32x2) ====== */
__global__ void __launch_bounds__(512, 1)
k_node1(const float* __restrict__ h, const float* __restrict__ nw1,
        const float* __restrict__ nb1) {
    float* sm = (float*)smraw;
    float* W  = sm;
    float* As = W + 32768;
    int tid = threadIdx.x, tr = tid >> 5, tc = tid & 31;

    for (int i = tid; i < 32768; i += 512) W[i] = nw1[i];
    int n0 = blockIdx.x * 64;
    for (int i = tid; i < 64 * 256; i += 512) {
        int r = i >> 8, k = i & 255, n = n0 + r;
        float v = 0.f;
        if (n < NN) v = (k < 128) ? g_mi[n * 128 + k] : h[n * 128 + (k - 128)];
        As[sidx(k, r)] = v;
    }
    __syncthreads();

    float acc[4][4];
#pragma unroll
    for (int e = 0; e < 4; e++)
#pragma unroll
        for (int j = 0; j < 4; j++) acc[e][j] = nb1[4 * tc + j];
    gemm_acc_f2<256>(As, W, acc, tr, tc);
#pragma unroll
    for (int e = 0; e < 4; e++) {
        int n = n0 + tr * 4 + e;
        if (n < NN)
            *(float4*)&g_tmp[n * 128 + 4 * tc] =
                make_float4(fmaxf(acc[e][0], 0.f), fmaxf(acc[e][1], 0.f),
                            fmaxf(acc[e][2], 0.f), fmaxf(acc[e][3], 0.f));
    }
}

/* ================= kernel C2: out = hidden@nw2+nb2 (f32x2) =============== */
__global__ void __launch_bounds__(512, 1)
k_node2(const float* __restrict__ nw2, const float* __restrict__ nb2,
        float* __restrict__ out) {
    float* sm = (float*)smraw;
    float* W  = sm;
    float* As = W + 16384;
    int tid = threadIdx.x, tr = tid >> 5, tc = tid & 31;

    for (int i = tid; i < 16384; i += 512) W[i] = nw2[i];
    int n0 = blockIdx.x * 64;
    for (int i = tid; i < 64 * 128; i += 512) {
        int r = i >> 7, k = i & 127, n = n0 + r;
        As[sidx(k, r)] = (n < NN) ? g_tmp[n * 128 + k] : 0.f;
    }
    __syncthreads();

    float acc[4][4];
#pragma unroll
    for (int e = 0; e < 4; e++)
#pragma unroll
        for (int j = 0; j < 4; j++) acc[e][j] = nb2[4 * tc + j];
    gemm_acc_f2<128>(As, W, acc, tr, tc);
#pragma unroll
    for (int e = 0; e < 4; e++) {
        int n = n0 + tr * 4 + e;
        if (n < NN)
            *(float4*)&out[n * 128 + 4 * tc] =
                make_float4(acc[e][0], acc[e][1], acc[e][2], acc[e][3]);
    }
}

/* ================= kernel X: x_out = x + dx/E ============================ */
__global__ void k_xupd(const float* __restrict__ x, float* __restrict__ out) {
    int i = blockIdx.x * blockDim.x + threadIdx.x;
    if (i < NN * 3)
        out[NN * 128 + i] = x[i] + g_dx[i] * (1.0f / (float)EE);
}

/* ========================================================================= */
extern "C" void kernel_launch(void* const* d_in, const int* in_sizes, int n_in,
                              void* d_out, int out_size) {
    const float* h    = (const float*)d_in[0];
    const float* x    = (const float*)d_in[1];
    const float* ea   = (const float*)d_in[2];
    const float* ew1  = (const float*)d_in[3];
    const float* eb1  = (const float*)d_in[4];
    const float* ew2  = (const float*)d_in[5];
    const float* eb2  = (const float*)d_in[6];
    const float* infw = (const float*)d_in[7];
    const float* infb = (const float*)d_in[8];
    const float* nw1  = (const float*)d_in[9];
    const float* nb1  = (const float*)d_in[10];
    const float* nw2  = (const float*)d_in[11];
    const float* nb2  = (const float*)d_in[12];
    const float* xw1  = (const float*)d_in[13];
    const float* xb1  = (const float*)d_in[14];
    const float* xw2  = (const float*)d_in[15];
    const float* xb2  = (const float*)d_in[16];
    const int*   ei   = (const int*)d_in[17];
    float* out = (float*)d_out;

    const size_t smA  = (16384 + 16384 + 8192) * sizeof(float);   /* 163840 */
    const size_t smC1 = (32768 + 16384) * sizeof(float);          /* 196608 */
    const size_t smC2 = (16384 + 8192) * sizeof(float);           /*  98304 */

    cudaFuncSetAttribute(k_node_pre, cudaFuncAttributeMaxDynamicSharedMemorySize, (int)smA);
    cudaFuncSetAttribute(k_edge,     cudaFuncAttributeMaxDynamicSharedMemorySize, SB_TOTAL);
    cudaFuncSetAttribute(k_node1,    cudaFuncAttributeMaxDynamicSharedMemorySize, (int)smC1);
    cudaFuncSetAttribute(k_node2,    cudaFuncAttributeMaxDynamicSharedMemorySize, (int)smC2);

    k_node_pre<<<NTILES_N, 512, smA>>>(h, ew1, eb1);
    k_edge<<<148, 512, SB_TOTAL>>>(x, ea, ew1, ew2, eb2, infw, infb,
                                   xw1, xb1, xw2, xb2, ei);
    k_node1<<<NTILES_N, 512, smC1>>>(h, nw1, nb1);
    k_node2<<<NTILES_N, 512, smC2>>>(nw2, nb2, out);
    k_xupd<<<(NN * 3 + 255) / 256, 256>>>(x, out);
}

// round 13
// speedup vs baseline: 1.3350x; 1.1546x over previous
#include <cuda_runtime.h>
#include <cuda_bf16.h>
#include <math.h>
#include <stdint.h>

#define NN 20000
#define EE 320000
#define HH 128
#define NTILES_N ((NN + 63) / 64)   /* 313 */
#define ETILE 128
#define NTILES_E (EE / ETILE)       /* 2500 */
#define GRIDN 148

extern __shared__ char smraw[];

/* ---------------- scratch (static device globals; no allocations) -------- */
__device__ float g_g1[NN * HH];
__device__ float g_g2[NN * HH];
__device__ float g_mi[NN * HH];
__device__ float g_tmp[NN * HH];
__device__ float g_dx[NN * 3];

/* ---------------- small helpers ------------------------------------------ */
__device__ __forceinline__ void red2(float* p, float a, float b) {
    asm volatile("red.global.add.v2.f32 [%0], {%1,%2};"
                 :: "l"(p), "f"(a), "f"(b) : "memory");
}
__device__ __forceinline__ uint32_t smem_u32(const void* p) {
    uint32_t a;
    asm("{ .reg .u64 t; cvta.to.shared.u64 t, %1; cvt.u32.u64 %0, t; }"
        : "=r"(a) : "l"(p));
    return a;
}
#define PACKBF2(res, a, b) \
    asm("cvt.rn.satfinite.bf16x2.f32 %0, %1, %2;" : "=r"(res) : "f"(b), "f"(a))
__device__ __forceinline__ void split2(float a0, float a1, uint32_t& hw, uint32_t& lw) {
    PACKBF2(hw, a0, a1);
    float h0 = __uint_as_float(hw << 16);
    float h1 = __uint_as_float(hw & 0xffff0000u);
    PACKBF2(lw, a0 - h0, a1 - h1);
}

/* ---------------- mma / ldmatrix ----------------------------------------- */
#define LDSM4(r, a) \
    asm volatile("ldmatrix.sync.aligned.m8n8.x4.shared.b16 {%0,%1,%2,%3},[%4];" \
        : "=r"((r)[0]), "=r"((r)[1]), "=r"((r)[2]), "=r"((r)[3]) : "r"(a))
#define MMA_B16(d, a, b0, b1) \
    asm volatile("mma.sync.aligned.m16n8k16.row.col.f32.bf16.bf16.f32 " \
        "{%0,%1,%2,%3},{%4,%5,%6,%7},{%8,%9},{%0,%1,%2,%3};" \
        : "+f"((d)[0]), "+f"((d)[1]), "+f"((d)[2]), "+f"((d)[3]) \
        : "r"((a)[0]), "r"((a)[1]), "r"((a)[2]), "r"((a)[3]), "r"(b0), "r"(b1))

__device__ __forceinline__ uint32_t pch(int c, int r) {
    return (uint32_t)((c & ~7) | ((c & 7) ^ (r & 7)));
}

/* warp GEMM: D[16*MBLK rows x 16*NJP cols] += A * B^T, acc[MBLK*2*NJP][4] */
template<int KSTEPS, bool X3, int CA, int CB, int MBLK, int NJP>
__device__ __forceinline__ void mma_gemm(const char* aH, const char* aL,
                                         const char* bH, const char* bL,
                                         float acc[][4], int wm, int wn, int lane) {
    int ar7 = lane & 7;
    int arow_in = ((lane >> 3) & 1) * 8 + ar7;
    int acoff = lane >> 4;
    int brow_l = ((lane >> 4) & 1) * 8 + ar7;
    int bcoff = (lane >> 3) & 1;
    uint32_t aHb = smem_u32(aH);
    uint32_t aLb = X3 ? smem_u32(aL) : 0u;
    uint32_t bHb = smem_u32(bH);
    uint32_t bLb = X3 ? smem_u32(bL) : 0u;
#pragma unroll
    for (int ks = 0; ks < KSTEPS; ks++) {
        uint32_t ah[MBLK][4], al[MBLK][4];
        uint32_t achoff = pch(2 * ks + acoff, ar7) * 16;
#pragma unroll
        for (int mb = 0; mb < MBLK; mb++) {
            int arow = 16 * MBLK * wm + 16 * mb + arow_in;
            LDSM4(ah[mb], aHb + (uint32_t)(arow * CA) + achoff);
            if (X3) LDSM4(al[mb], aLb + (uint32_t)(arow * CA) + achoff);
        }
        uint32_t boff = pch(2 * ks + bcoff, ar7) * 16;
#pragma unroll
        for (int jp = 0; jp < NJP; jp++) {
            uint32_t brb = (uint32_t)((wn * (16 * NJP) + jp * 16 + brow_l) * CB) + boff;
            uint32_t bh[4], bl[4];
            LDSM4(bh, bHb + brb);
            if (X3) LDSM4(bl, bLb + brb);
#pragma unroll
            for (int mb = 0; mb < MBLK; mb++) {
                float* a0 = acc[mb * 2 * NJP + 2 * jp];
                float* a1 = acc[mb * 2 * NJP + 2 * jp + 1];
                MMA_B16(a0, ah[mb], bh[0], bh[1]);
                MMA_B16(a1, ah[mb], bh[2], bh[3]);
                if (X3) {
                    MMA_B16(a0, al[mb], bh[0], bh[1]);
                    MMA_B16(a1, al[mb], bh[2], bh[3]);
                    MMA_B16(a0, ah[mb], bl[0], bl[1]);
                    MMA_B16(a1, ah[mb], bl[2], bl[3]);
                }
            }
        }
    }
}

/* ================= kernel A: node precompute (MMA, grid-stride) ========== */
/* smem: W1H 0 W1L 32K W2H 64K W2L 96K AH 128K(16K) AL 144K  total 163840 */
#define P_W1H 0
#define P_W1L 32768
#define P_W2H 65536
#define P_W2L 98304
#define P_AH  131072
#define P_AL  147456
#define P_TOT 163840

__global__ void __launch_bounds__(512, 1)
k_node_pre(const float* __restrict__ h, const float* __restrict__ ew1,
           const float* __restrict__ eb1) {
    char* sm = smraw;
    int tid = threadIdx.x, lane = tid & 31, wid = tid >> 5;
    int wm = wid >> 2, wn = wid & 3;
    int gtid = blockIdx.x * 512 + tid;

    /* zero scratch accumulators (whole arrays, grid-stride) */
    for (int i = gtid; i < NN * HH; i += GRIDN * 512) g_mi[i] = 0.f;
    for (int i = gtid; i < NN * 3; i += GRIDN * 512) g_dx[i] = 0.f;

    /* weights: W1[n][k]=ew1[(48+k)*128+n], W2[n][k]=ew1[(176+k)*128+n] */
    for (int i = tid; i < 128 * 64; i += 512) {
        int n = i >> 6, kp = i & 63, k = 2 * kp;
        uint32_t off = (uint32_t)(n * 256) + pch(k >> 3, n) * 16 + (k & 7) * 2;
        uint32_t hw, lw;
        split2(ew1[(48 + k) * 128 + n], ew1[(49 + k) * 128 + n], hw, lw);
        *(uint32_t*)(sm + P_W1H + off) = hw;
        *(uint32_t*)(sm + P_W1L + off) = lw;
        split2(ew1[(176 + k) * 128 + n], ew1[(177 + k) * 128 + n], hw, lw);
        *(uint32_t*)(sm + P_W2H + off) = hw;
        *(uint32_t*)(sm + P_W2L + off) = lw;
    }
    __syncthreads();

    int r0 = 16 * wm + (lane >> 2), r1 = r0 + 8;

    for (int t = blockIdx.x; t < NTILES_N; t += GRIDN) {
        int n0 = t * 64;
        for (int i = tid; i < 64 * 64; i += 512) {
            int r = i >> 6, kp = i & 63, k = 2 * kp, n = n0 + r;
            float2 v = (n < NN) ? *(const float2*)&h[(size_t)n * 128 + k]
                                : make_float2(0.f, 0.f);
            uint32_t hw, lw; split2(v.x, v.y, hw, lw);
            uint32_t off = (uint32_t)(r * 256) + pch(k >> 3, r) * 16 + (k & 7) * 2;
            *(uint32_t*)(sm + P_AH + off) = hw;
            *(uint32_t*)(sm + P_AL + off) = lw;
        }
        __syncthreads();

        float acc[4][4];
#pragma unroll
        for (int j = 0; j < 4; j++)
#pragma unroll
            for (int q = 0; q < 4; q++) acc[j][q] = 0.f;
        mma_gemm<8, true, 256, 256, 1, 2>(sm + P_AH, sm + P_AL,
                                          sm + P_W1H, sm + P_W1L, acc, wm, wn, lane);
#pragma unroll
        for (int j = 0; j < 4; j++) {
            int col = 32 * wn + 8 * j + 2 * (lane & 3);
            float2 b = __ldg((const float2*)(eb1 + col));
            if (n0 + r0 < NN)
                *(float2*)&g_g1[(size_t)(n0 + r0) * 128 + col] =
                    make_float2(acc[j][0] + b.x, acc[j][1] + b.y);
            if (n0 + r1 < NN)
                *(float2*)&g_g1[(size_t)(n0 + r1) * 128 + col] =
                    make_float2(acc[j][2] + b.x, acc[j][3] + b.y);
        }
#pragma unroll
        for (int j = 0; j < 4; j++)
#pragma unroll
            for (int q = 0; q < 4; q++) acc[j][q] = 0.f;
        mma_gemm<8, true, 256, 256, 1, 2>(sm + P_AH, sm + P_AL,
                                          sm + P_W2H, sm + P_W2L, acc, wm, wn, lane);
#pragma unroll
        for (int j = 0; j < 4; j++) {
            int col = 32 * wn + 8 * j + 2 * (lane & 3);
            if (n0 + r0 < NN)
                *(float2*)&g_g2[(size_t)(n0 + r0) * 128 + col] =
                    make_float2(acc[j][0], acc[j][1]);
            if (n0 + r1 < NN)
                *(float2*)&g_g2[(size_t)(n0 + r1) * 128 + col] =
                    make_float2(acc[j][2], acc[j][3]);
        }
        __syncthreads();
    }
}

/* ================= kernel B: edge pipeline (4 syncs/tile) ================ */
#define SB_PDB   512      /* 2048  : [128 rows][4 wn] f32 (gate) */
#define SB_FEATH 2560     /* 16384 */
#define SB_FEATL 18944    /* 16384 */
#define SB_BUFM  2560     /* 32768 overlays feat */
#define SB_TH    35328    /* 32768 */
#define SB_TL    68096    /* 32768 */
#define SB_W1H   100864   /* 16384 */
#define SB_W1L   117248
#define SB_W2H   133632   /* 32768 */
#define SB_W2L   166400
#define SB_W3    199168
#define SB_TOTAL 231936

__global__ void __launch_bounds__(512, 1)
k_edge(const float* __restrict__ x, const float* __restrict__ eattr,
       const float* __restrict__ ew1, const float* __restrict__ ew2,
       const float* __restrict__ eb2, const float* __restrict__ infw,
       const float* __restrict__ infb, const float* __restrict__ xw1,
       const float* __restrict__ xb1, const float* __restrict__ xw2,
       const float* __restrict__ xb2, const int* __restrict__ eidx) {
    char* sm = smraw;
    float* pdb = (float*)(sm + SB_PDB);

    int tid = threadIdx.x;
    int lane = tid & 31;
    int wid = tid >> 5;
    int wm = wid >> 2, wn = wid & 3;

    for (int i = tid; i < 128 * 64; i += 512) {
        int n = i >> 6, k = i & 63;
        float v = (k < 48) ? ew1[k * 128 + n] : 0.f;
        __nv_bfloat16 hb = __float2bfloat16(v);
        uint32_t off = (uint32_t)(n * 128) + pch(k >> 3, n) * 16 + (k & 7) * 2;
        *(__nv_bfloat16*)(sm + SB_W1H + off) = hb;
        *(__nv_bfloat16*)(sm + SB_W1L + off) =
            __float2bfloat16(v - __bfloat162float(hb));
    }
    for (int i = tid; i < 128 * 128; i += 512) {
        int n = i >> 7, k = i & 127;
        uint32_t off = (uint32_t)(n * 256) + pch(k >> 3, n) * 16 + (k & 7) * 2;
        float v = ew2[k * 128 + n];
        __nv_bfloat16 hb = __float2bfloat16(v);
        *(__nv_bfloat16*)(sm + SB_W2H + off) = hb;
        *(__nv_bfloat16*)(sm + SB_W2L + off) =
            __float2bfloat16(v - __bfloat162float(hb));
        *(__nv_bfloat16*)(sm + SB_W3 + off) = __float2bfloat16(xw1[k * 128 + n]);
    }
    __syncthreads();

    const float infbv = infb[0];
    const float xb2v  = xb2[0];
    const float step  = 100.0f / 19.0f;
    const float coeff = -0.5f / (step * step);

    int rowq[4];
#pragma unroll
    for (int q = 0; q < 4; q++)
        rowq[q] = 32 * wm + 16 * (q >> 1) + (lane >> 2) + 8 * (q & 1);

    for (int tile = blockIdx.x; tile < NTILES_E; tile += gridDim.x) {
        __syncthreads();                      /* s0: prev GEMM3 bufM reads done */
        int e0 = tile * ETILE;

        if (tid < 128) {
            int e = e0 + tid;
            int d = __ldg(&eidx[e]), s = __ldg(&eidx[EE + e]);
            float rx = x[d * 3 + 0] - x[s * 3 + 0];
            float ry = x[d * 3 + 1] - x[s * 3 + 1];
            float rz = x[d * 3 + 2] - x[s * 3 + 2];
            float l2 = sqrtf(rx * rx + ry * ry + rz * rz);
#pragma unroll
            for (int kk = 0; kk < 10; kk++) {
                int w = 14 + kk;
                float d0 = l2 - (float)(2 * kk) * step;
                float d1 = l2 - (float)(2 * kk + 1) * step;
                uint32_t hw, lw;
                split2(expf(coeff * d0 * d0), expf(coeff * d1 * d1), hw, lw);
                uint32_t off = (uint32_t)(tid * 128) + pch(w >> 2, tid) * 16 + (w & 3) * 4;
                *(uint32_t*)(sm + SB_FEATH + off) = hw;
                *(uint32_t*)(sm + SB_FEATL + off) = lw;
            }
        }
        for (int i = tid; i < 128 * 14; i += 512) {
            int e = i / 14, w = i - 14 * e;
            float2 t = *(const float2*)&eattr[(size_t)(e0 + e) * 28 + 2 * w];
            uint32_t hw, lw; split2(t.x, t.y, hw, lw);
            uint32_t off = (uint32_t)(e * 128) + pch(w >> 2, e) * 16 + (w & 3) * 4;
            *(uint32_t*)(sm + SB_FEATH + off) = hw;
            *(uint32_t*)(sm + SB_FEATL + off) = lw;
        }
        __syncthreads();                      /* s2: feat ready */

        int dR[4], sR[4];
#pragma unroll
        for (int q = 0; q < 4; q++) {
            dR[q] = __ldg(&eidx[e0 + rowq[q]]);
            sR[q] = __ldg(&eidx[EE + e0 + rowq[q]]);
        }

        /* ---- GEMM1 (K=48, bf16x3) ---- */
        float acc[8][4];
#pragma unroll
        for (int j = 0; j < 8; j++)
#pragma unroll
            for (int q = 0; q < 4; q++) acc[j][q] = 0.f;
        mma_gemm<3, true, 128, 128, 2, 2>(sm + SB_FEATH, sm + SB_FEATL,
                                          sm + SB_W1H, sm + SB_W1L, acc, wm, wn, lane);

        /* ---- ep1: t1 = relu(D + g1[d] + g2[s]) -> TH/TL ---- */
#pragma unroll
        for (int q = 0; q < 4; q++) {
            const float* g1p = g_g1 + (size_t)dR[q] * 128;
            const float* g2p = g_g2 + (size_t)sR[q] * 128;
            int row = rowq[q];
            int e01 = (q & 1) * 2;
#pragma unroll
            for (int j = 0; j < 4; j++) {
                int col = 32 * wn + 8 * j + 2 * (lane & 3);
                float2 a = *(const float2*)(g1p + col);
                float2 b = *(const float2*)(g2p + col);
                float* ac = acc[(q >> 1) * 4 + j];
                float v0 = fmaxf(ac[e01] + a.x + b.x, 0.f);
                float v1 = fmaxf(ac[e01 + 1] + a.y + b.y, 0.f);
                uint32_t hw, lw; split2(v0, v1, hw, lw);
                uint32_t off = (uint32_t)(row * 256) + pch(col >> 3, row) * 16 + (col & 7) * 2;
                *(uint32_t*)(sm + SB_TH + off) = hw;
                *(uint32_t*)(sm + SB_TL + off) = lw;
            }
        }
        __syncthreads();                      /* s_T */

        /* ---- GEMM2 (K=128, bf16x3) ---- */
#pragma unroll
        for (int j = 0; j < 8; j++)
#pragma unroll
            for (int q = 0; q < 4; q++) acc[j][q] = 0.f;
        mma_gemm<8, true, 256, 256, 2, 2>(sm + SB_TH, sm + SB_TL,
                                          sm + SB_W2H, sm + SB_W2L, acc, wm, wn, lane);

        /* ---- ep2a: mij = relu(D+eb2); gate partials -> pdb; bufM ---- */
        float pdv[4] = {0.f, 0.f, 0.f, 0.f};
#pragma unroll
        for (int j = 0; j < 4; j++) {
            int col = 32 * wn + 8 * j + 2 * (lane & 3);
            float2 be = __ldg((const float2*)(eb2 + col));
            float2 iw = __ldg((const float2*)(infw + col));
#pragma unroll
            for (int q = 0; q < 4; q++) {
                float* ac = acc[(q >> 1) * 4 + j];
                int e01 = (q & 1) * 2;
                float m0 = fmaxf(ac[e01] + be.x, 0.f);
                float m1 = fmaxf(ac[e01 + 1] + be.y, 0.f);
                ac[e01] = m0; ac[e01 + 1] = m1;
                pdv[q] += m0 * iw.x + m1 * iw.y;
                uint32_t w; PACKBF2(w, m0, m1);
                int row = rowq[q];
                uint32_t off = (uint32_t)(row * 256) + pch(col >> 3, row) * 16 + (col & 7) * 2;
                *(uint32_t*)(sm + SB_BUFM + off) = w;
            }
        }
#pragma unroll
        for (int o = 1; o <= 2; o <<= 1)
#pragma unroll
            for (int q = 0; q < 4; q++)
                pdv[q] += __shfl_xor_sync(0xffffffffu, pdv[q], o);
        if ((lane & 3) == 0) {
#pragma unroll
            for (int q = 0; q < 4; q++)
                pdb[rowq[q] * 4 + wn] = pdv[q];
        }
        __syncthreads();                      /* s_pd */

        /* ---- ep2b: eij; scatter mi ---- */
#pragma unroll
        for (int q = 0; q < 4; q++) {
            float4 p = *(const float4*)(pdb + rowq[q] * 4);
            float eij = 1.f / (1.f + expf(-(p.x + p.y + p.z + p.w + infbv)));
            float* mip = g_mi + (size_t)dR[q] * 128;
            int e01 = (q & 1) * 2;
#pragma unroll
            for (int j = 0; j < 4; j++) {
                int col = 32 * wn + 8 * j + 2 * (lane & 3);
                float* ac = acc[(q >> 1) * 4 + j];
                red2(mip + col, ac[e01] * eij, ac[e01 + 1] * eij);
            }
        }

        /* ---- GEMM3 (K=128, bf16 x1) ---- */
#pragma unroll
        for (int j = 0; j < 8; j++)
#pragma unroll
            for (int q = 0; q < 4; q++) acc[j][q] = 0.f;
        mma_gemm<8, false, 256, 256, 2, 2>(sm + SB_BUFM, 0,
                                           sm + SB_W3, 0, acc, wm, wn, lane);

        /* ---- ep3: per-wn xg partial scattered directly to g_dx ---- */
        float qv[4] = {0.f, 0.f, 0.f, 0.f};
#pragma unroll
        for (int j = 0; j < 4; j++) {
            int col = 32 * wn + 8 * j + 2 * (lane & 3);
            float2 xb = __ldg((const float2*)(xb1 + col));
            float2 xw = __ldg((const float2*)(xw2 + col));
#pragma unroll
            for (int q = 0; q < 4; q++) {
                float* ac = acc[(q >> 1) * 4 + j];
                int e01 = (q & 1) * 2;
                qv[q] += fmaxf(ac[e01] + xb.x, 0.f) * xw.x
                       + fmaxf(ac[e01 + 1] + xb.y, 0.f) * xw.y;
            }
        }
#pragma unroll
        for (int o = 1; o <= 2; o <<= 1)
#pragma unroll
            for (int q = 0; q < 4; q++)
                qv[q] += __shfl_xor_sync(0xffffffffu, qv[q], o);
        if ((lane & 3) == 0) {
            float base = (wn == 0) ? xb2v : 0.f;
#pragma unroll
            for (int q = 0; q < 4; q++) {
                float xg = qv[q] + base;
                int d = dR[q], s = sR[q];
                float rx = __ldg(&x[d * 3 + 0]) - __ldg(&x[s * 3 + 0]);
                float ry = __ldg(&x[d * 3 + 1]) - __ldg(&x[s * 3 + 1]);
                float rz = __ldg(&x[d * 3 + 2]) - __ldg(&x[s * 3 + 2]);
                atomicAdd(&g_dx[d * 3 + 0], rx * xg);
                atomicAdd(&g_dx[d * 3 + 1], ry * xg);
                atomicAdd(&g_dx[d * 3 + 2], rz * xg);
            }
        }
    }
}

/* ================= kernel C1: hidden = relu([mi,h]@nw1+nb1) (MMA) ======== */
/* smem: WH 0(64K) WL 64K AH 128K(32K) AL 160K  total 196608 */
#define N1_WH 0
#define N1_WL 65536
#define N1_AH 131072
#define N1_AL 163840
#define N1_TOT 196608

__global__ void __launch_bounds__(512, 1)
k_node1(const float* __restrict__ h, const float* __restrict__ nw1,
        const float* __restrict__ nb1) {
    char* sm = smraw;
    int tid = threadIdx.x, lane = tid & 31, wid = tid >> 5;
    int wm = wid >> 2, wn = wid & 3;

    for (int i = tid; i < 128 * 128; i += 512) {
        int n = i >> 7, kp = i & 127, k = 2 * kp;
        uint32_t off = (uint32_t)(n * 512) + pch(k >> 3, n) * 16 + (k & 7) * 2;
        uint32_t hw, lw;
        split2(nw1[k * 128 + n], nw1[(k + 1) * 128 + n], hw, lw);
        *(uint32_t*)(sm + N1_WH + off) = hw;
        *(uint32_t*)(sm + N1_WL + off) = lw;
    }
    __syncthreads();

    int r0 = 16 * wm + (lane >> 2), r1 = r0 + 8;

    for (int t = blockIdx.x; t < NTILES_N; t += GRIDN) {
        int n0 = t * 64;
        for (int i = tid; i < 64 * 128; i += 512) {
            int r = i >> 7, kp = i & 127, k = 2 * kp, n = n0 + r;
            float2 v = make_float2(0.f, 0.f);
            if (n < NN)
                v = (k < 128) ? *(const float2*)&g_mi[(size_t)n * 128 + k]
                              : *(const float2*)&h[(size_t)n * 128 + (k - 128)];
            uint32_t hw, lw; split2(v.x, v.y, hw, lw);
            uint32_t off = (uint32_t)(r * 512) + pch(k >> 3, r) * 16 + (k & 7) * 2;
            *(uint32_t*)(sm + N1_AH + off) = hw;
            *(uint32_t*)(sm + N1_AL + off) = lw;
        }
        __syncthreads();

        float acc[4][4];
#pragma unroll
        for (int j = 0; j < 4; j++)
#pragma unroll
            for (int q = 0; q < 4; q++) acc[j][q] = 0.f;
        mma_gemm<16, true, 512, 512, 1, 2>(sm + N1_AH, sm + N1_AL,
                                           sm + N1_WH, sm + N1_WL, acc, wm, wn, lane);
#pragma unroll
        for (int j = 0; j < 4; j++) {
            int col = 32 * wn + 8 * j + 2 * (lane & 3);
            float2 b = __ldg((const float2*)(nb1 + col));
            if (n0 + r0 < NN)
                *(float2*)&g_tmp[(size_t)(n0 + r0) * 128 + col] =
                    make_float2(fmaxf(acc[j][0] + b.x, 0.f), fmaxf(acc[j][1] + b.y, 0.f));
            if (n0 + r1 < NN)
                *(float2*)&g_tmp[(size_t)(n0 + r1) * 128 + col] =
                    make_float2(fmaxf(acc[j][2] + b.x, 0.f), fmaxf(acc[j][3] + b.y, 0.f));
        }
        __syncthreads();
    }
}

/* ================= kernel C2: out = hidden@nw2+nb2 (MMA) + xupd ========== */
/* smem: WH 0(32K) WL 32K AH 64K(16K) AL 80K  total 98304 */
#define N2_WH 0
#define N2_WL 32768
#define N2_AH 65536
#define N2_AL 81920
#define N2_TOT 98304

__global__ void __launch_bounds__(512, 1)
k_node2(const float* __restrict__ nw2, const float* __restrict__ nb2,
        const float* __restrict__ x, float* __restrict__ out) {
    char* sm = smraw;
    int tid = threadIdx.x, lane = tid & 31, wid = tid >> 5;
    int wm = wid >> 2, wn = wid & 3;
    int gtid = blockIdx.x * 512 + tid;

    /* fused x update */
    for (int i = gtid; i < NN * 3; i += GRIDN * 512)
        out[NN * 128 + i] = x[i] + g_dx[i] * (1.0f / (float)EE);

    for (int i = tid; i < 128 * 64; i += 512) {
        int n = i >> 6, kp = i & 63, k = 2 * kp;
        uint32_t off = (uint32_t)(n * 256) + pch(k >> 3, n) * 16 + (k & 7) * 2;
        uint32_t hw, lw;
        split2(nw2[k * 128 + n], nw2[(k + 1) * 128 + n], hw, lw);
        *(uint32_t*)(sm + N2_WH + off) = hw;
        *(uint32_t*)(sm + N2_WL + off) = lw;
    }
    __syncthreads();

    int r0 = 16 * wm + (lane >> 2), r1 = r0 + 8;

    for (int t = blockIdx.x; t < NTILES_N; t += GRIDN) {
        int n0 = t * 64;
        for (int i = tid; i < 64 * 64; i += 512) {
            int r = i >> 6, kp = i & 63, k = 2 * kp, n = n0 + r;
            float2 v = (n < NN) ? *(const float2*)&g_tmp[(size_t)n * 128 + k]
                                : make_float2(0.f, 0.f);
            uint32_t hw, lw; split2(v.x, v.y, hw, lw);
            uint32_t off = (uint32_t)(r * 256) + pch(k >> 3, r) * 16 + (k & 7) * 2;
            *(uint32_t*)(sm + N2_AH + off) = hw;
            *(uint32_t*)(sm + N2_AL + off) = lw;
        }
        __syncthreads();

        float acc[4][4];
#pragma unroll
        for (int j = 0; j < 4; j++)
#pragma unroll
            for (int q = 0; q < 4; q++) acc[j][q] = 0.f;
        mma_gemm<8, true, 256, 256, 1, 2>(sm + N2_AH, sm + N2_AL,
                                          sm + N2_WH, sm + N2_WL, acc, wm, wn, lane);
#pragma unroll
        for (int j = 0; j < 4; j++) {
            int col = 32 * wn + 8 * j + 2 * (lane & 3);
            float2 b = __ldg((const float2*)(nb2 + col));
            if (n0 + r0 < NN)
                *(float2*)&out[(size_t)(n0 + r0) * 128 + col] =
                    make_float2(acc[j][0] + b.x, acc[j][1] + b.y);
            if (n0 + r1 < NN)
                *(float2*)&out[(size_t)(n0 + r1) * 128 + col] =
                    make_float2(acc[j][2] + b.x, acc[j][3] + b.y);
        }
        __syncthreads();
    }
}

/* ========================================================================= */
extern "C" void kernel_launch(void* const* d_in, const int* in_sizes, int n_in,
                              void* d_out, int out_size) {
    const float* h    = (const float*)d_in[0];
    const float* x    = (const float*)d_in[1];
    const float* ea   = (const float*)d_in[2];
    const float* ew1  = (const float*)d_in[3];
    const float* eb1  = (const float*)d_in[4];
    const float* ew2  = (const float*)d_in[5];
    const float* eb2  = (const float*)d_in[6];
    const float* infw = (const float*)d_in[7];
    const float* infb = (const float*)d_in[8];
    const float* nw1  = (const float*)d_in[9];
    const float* nb1  = (const float*)d_in[10];
    const float* nw2  = (const float*)d_in[11];
    const float* nb2  = (const float*)d_in[12];
    const float* xw1  = (const float*)d_in[13];
    const float* xb1  = (const float*)d_in[14];
    const float* xw2  = (const float*)d_in[15];
    const float* xb2  = (const float*)d_in[16];
    const int*   ei   = (const int*)d_in[17];
    float* out = (float*)d_out;

    cudaFuncSetAttribute(k_node_pre, cudaFuncAttributeMaxDynamicSharedMemorySize, P_TOT);
    cudaFuncSetAttribute(k_edge,     cudaFuncAttributeMaxDynamicSharedMemorySize, SB_TOTAL);
    cudaFuncSetAttribute(k_node1,    cudaFuncAttributeMaxDynamicSharedMemorySize, N1_TOT);
    cudaFuncSetAttribute(k_node2,    cudaFuncAttributeMaxDynamicSharedMemorySize, N2_TOT);

    k_node_pre<<<GRIDN, 512, P_TOT>>>(h, ew1, eb1);
    k_edge<<<GRIDN, 512, SB_TOTAL>>>(x, ea, ew1, ew2, eb2, infw, infb,
                                     xw1, xb1, xw2, xb2, ei);
    k_node1<<<GRIDN, 512, N1_TOT>>>(h, nw1, nb1);
    k_node2<<<GRIDN, 512, N2_TOT>>>(nw2, nb2, x, out);
}